// round 1
// baseline (speedup 1.0000x reference)
#include <cuda_runtime.h>
#include <math.h>

// Problem constants (fixed by setup_inputs)
#define BATCH 4
#define HDIM 128
#define WDIM 128
#define CDIM 256
#define HIDDIM 1024
#define LTOK 16384              // H*W
#define NTOK 65536              // B*L
#define WINS 8
#define NWIN 64                 // tokens per window
#define NWSIDE 16
#define HEADS 8
#define HDHEAD 32

// ---------------- scratch (device globals; no allocations allowed) ----------
__device__ float g_xwin[NTOK * CDIM];        // LN1 output in window-token layout
__device__ float g_q[NTOK * CDIM];           // q (scaled)
__device__ float g_kv[NTOK * 2 * CDIM];      // k | v
__device__ float g_o[NTOK * CDIM];           // attention output (window layout)
__device__ float g_proj[NTOK * CDIM];        // proj output (window layout)
__device__ float g_x1[NTOK * CDIM];          // residual-1 result (token layout)
__device__ float g_h[NTOK * HIDDIM];         // lin1+gelu output (NHWC)
__device__ float g_h2[NTOK * HIDDIM];        // dwconv+gelu output

// ---------------- LN1 + shifted-window gather -------------------------------
// window token wt -> source token: ((wh*8+i+4)&127, (ww*8+j+4)&127)
__global__ void k_ln1_gather(const float* __restrict__ x,
                             const float* __restrict__ w,
                             const float* __restrict__ b) {
    int wt  = blockIdx.x;
    int bb  = wt >> 14;
    int rem = wt & 16383;
    int win = rem >> 6, n = rem & 63;
    int wh = win >> 4, ww = win & 15;
    int i = n >> 3, j = n & 7;
    int h  = (wh * 8 + i + 4) & 127;
    int wc = (ww * 8 + j + 4) & 127;
    const float* src = x + ((size_t)(bb * LTOK + h * WDIM + wc)) * CDIM;
    int c = threadIdx.x;
    float v = src[c];
    float s = v, s2 = v * v;
    #pragma unroll
    for (int o = 16; o > 0; o >>= 1) {
        s  += __shfl_down_sync(0xffffffffu, s, o);
        s2 += __shfl_down_sync(0xffffffffu, s2, o);
    }
    __shared__ float sm[8], sm2[8];
    __shared__ float mean_s, rstd_s;
    if ((c & 31) == 0) { sm[c >> 5] = s; sm2[c >> 5] = s2; }
    __syncthreads();
    if (c == 0) {
        float ts = 0.f, ts2 = 0.f;
        #pragma unroll
        for (int k2 = 0; k2 < 8; k2++) { ts += sm[k2]; ts2 += sm2[k2]; }
        float m   = ts * (1.f / 256.f);
        float var = ts2 * (1.f / 256.f) - m * m;
        mean_s = m;
        rstd_s = rsqrtf(var + 1e-5f);
    }
    __syncthreads();
    g_xwin[(size_t)wt * CDIM + c] = (v - mean_s) * rstd_s * w[c] + b[c];
}

// ---------------- LN2 (token layout, g_x1 -> g_xwin) ------------------------
__global__ void k_ln2(const float* __restrict__ w, const float* __restrict__ b) {
    int t = blockIdx.x;
    int c = threadIdx.x;
    float v = g_x1[(size_t)t * CDIM + c];
    float s = v, s2 = v * v;
    #pragma unroll
    for (int o = 16; o > 0; o >>= 1) {
        s  += __shfl_down_sync(0xffffffffu, s, o);
        s2 += __shfl_down_sync(0xffffffffu, s2, o);
    }
    __shared__ float sm[8], sm2[8];
    __shared__ float mean_s, rstd_s;
    if ((c & 31) == 0) { sm[c >> 5] = s; sm2[c >> 5] = s2; }
    __syncthreads();
    if (c == 0) {
        float ts = 0.f, ts2 = 0.f;
        #pragma unroll
        for (int k2 = 0; k2 < 8; k2++) { ts += sm[k2]; ts2 += sm2[k2]; }
        float m   = ts * (1.f / 256.f);
        float var = ts2 * (1.f / 256.f) - m * m;
        mean_s = m;
        rstd_s = rsqrtf(var + 1e-5f);
    }
    __syncthreads();
    g_xwin[(size_t)t * CDIM + c] = (v - mean_s) * rstd_s * w[c] + b[c];
}

// ---------------- SGEMM: C = A[MxK] @ B[KxN] + bias, epilogues --------------
// EPI: 0 = +bias; 1 = (+bias)*scale; 2 = gelu(+bias); 3 = +bias + residual
template <int EPI>
__global__ void __launch_bounds__(256) k_gemm(
    const float* __restrict__ A, const float* __restrict__ Bm,
    const float* __restrict__ bias, float* __restrict__ Cm,
    int M, int Nn, int K, float scale, const float* __restrict__ res)
{
    __shared__ float As[8][128];
    __shared__ float Bs[8][128];
    int tid = threadIdx.x;
    int bm = blockIdx.y << 7, bn = blockIdx.x << 7;
    int tx = tid & 15, ty = tid >> 4;
    float acc[8][8];
    #pragma unroll
    for (int i = 0; i < 8; i++)
        #pragma unroll
        for (int j = 0; j < 8; j++) acc[i][j] = 0.f;

    int arow = tid >> 1, aseg = (tid & 1) << 2;
    int bk = tid >> 5, bn4 = (tid & 31) << 2;
    const float* Aptr = A + (size_t)(bm + arow) * K + aseg;
    const float* Bptr = Bm + (size_t)bk * Nn + bn + bn4;

    for (int k0 = 0; k0 < K; k0 += 8) {
        float4 a4 = *(const float4*)(Aptr + k0);
        As[aseg + 0][arow] = a4.x;
        As[aseg + 1][arow] = a4.y;
        As[aseg + 2][arow] = a4.z;
        As[aseg + 3][arow] = a4.w;
        float4 b4 = *(const float4*)(Bptr + (size_t)k0 * Nn);
        *(float4*)&Bs[bk][bn4] = b4;
        __syncthreads();
        #pragma unroll
        for (int k = 0; k < 8; k++) {
            float4 a0 = *(const float4*)&As[k][ty * 8];
            float4 a1 = *(const float4*)&As[k][ty * 8 + 4];
            float4 b0 = *(const float4*)&Bs[k][tx * 8];
            float4 b1 = *(const float4*)&Bs[k][tx * 8 + 4];
            float af[8] = {a0.x, a0.y, a0.z, a0.w, a1.x, a1.y, a1.z, a1.w};
            float bf[8] = {b0.x, b0.y, b0.z, b0.w, b1.x, b1.y, b1.z, b1.w};
            #pragma unroll
            for (int i = 0; i < 8; i++)
                #pragma unroll
                for (int j = 0; j < 8; j++)
                    acc[i][j] = fmaf(af[i], bf[j], acc[i][j]);
        }
        __syncthreads();
    }
    #pragma unroll
    for (int i = 0; i < 8; i++) {
        int row = bm + ty * 8 + i;
        #pragma unroll
        for (int j = 0; j < 8; j++) {
            int col = bn + tx * 8 + j;
            float v = acc[i][j] + bias[col];
            if (EPI == 1) v *= scale;
            if (EPI == 2) v = 0.5f * v * (1.f + erff(v * 0.70710678118654752f));
            if (EPI == 3) v += res[(size_t)row * Nn + col];
            Cm[(size_t)row * Nn + col] = v;
        }
    }
}

// ---------------- fused windowed attention ----------------------------------
// grid = Bw*HEADS = 8192 blocks; one block = (window, head).
// QK^T + rel-pos bias + shift mask + softmax + PV in shared memory.
__global__ void __launch_bounds__(256) k_attn(const float* __restrict__ rpb) {
    int blk   = blockIdx.x;
    int head  = blk & 7;
    int wglob = blk >> 3;          // b*256 + win
    int win   = wglob & 255;
    int wh = win >> 4, ww = win & 15;
    int wt0 = wglob << 6;

    __shared__ float qs[64][33], ks[64][33], vs[64][33];
    __shared__ float at[64][65];

    int tid = threadIdx.x;
    for (int e = tid; e < 2048; e += 256) {
        int n = e >> 5, d = e & 31;
        qs[n][d] = g_q [(size_t)(wt0 + n) * CDIM + head * HDHEAD + d];
        ks[n][d] = g_kv[(size_t)(wt0 + n) * (2 * CDIM) + head * HDHEAD + d];
        vs[n][d] = g_kv[(size_t)(wt0 + n) * (2 * CDIM) + CDIM + head * HDHEAD + d];
    }
    __syncthreads();

    int r = tid >> 2, cg = tid & 3;
    int ir = r >> 3, jr = r & 7;
    // region class (shift mask): only edge windows (wh==15 / ww==15) mix regions
    int regr = ((wh == 15) ? (ir < 4 ? 1 : 2) : 0) * 3 +
               ((ww == 15) ? (jr < 4 ? 1 : 2) : 0);

    float av[16];
    float mx = -1e30f;
    #pragma unroll
    for (int cc = 0; cc < 16; cc++) {
        int c = cg * 16 + cc;
        float s = 0.f;
        #pragma unroll
        for (int d = 0; d < 32; d++) s = fmaf(qs[r][d], ks[c][d], s);
        int ic = c >> 3, jc = c & 7;
        s += rpb[((ir - ic + 7) * 15 + (jr - jc + 7)) * HEADS + head];
        int regc = ((wh == 15) ? (ic < 4 ? 1 : 2) : 0) * 3 +
                   ((ww == 15) ? (jc < 4 ? 1 : 2) : 0);
        if (regc != regr) s -= 100.f;
        av[cc] = s;
        mx = fmaxf(mx, s);
    }
    mx = fmaxf(mx, __shfl_xor_sync(0xffffffffu, mx, 1));
    mx = fmaxf(mx, __shfl_xor_sync(0xffffffffu, mx, 2));
    float sum = 0.f;
    #pragma unroll
    for (int cc = 0; cc < 16; cc++) { av[cc] = expf(av[cc] - mx); sum += av[cc]; }
    sum += __shfl_xor_sync(0xffffffffu, sum, 1);
    sum += __shfl_xor_sync(0xffffffffu, sum, 2);
    float inv = 1.f / sum;
    #pragma unroll
    for (int cc = 0; cc < 16; cc++) at[r][cg * 16 + cc] = av[cc] * inv;
    __syncthreads();

    float o[8] = {0.f, 0.f, 0.f, 0.f, 0.f, 0.f, 0.f, 0.f};
    #pragma unroll
    for (int m = 0; m < 64; m++) {
        float a = at[r][m];
        #pragma unroll
        for (int d = 0; d < 8; d++) o[d] = fmaf(a, vs[m][cg * 8 + d], o[d]);
    }
    #pragma unroll
    for (int d = 0; d < 8; d++)
        g_o[(size_t)(wt0 + r) * CDIM + head * HDHEAD + cg * 8 + d] = o[d];
}

// ---------------- reverse window + unshift + residual -----------------------
__global__ void k_scatter(const float* __restrict__ x) {
    int wt  = blockIdx.x;
    int bb  = wt >> 14;
    int rem = wt & 16383;
    int win = rem >> 6, n = rem & 63;
    int wh = win >> 4, ww = win & 15;
    int i = n >> 3, j = n & 7;
    int h  = (wh * 8 + i + 4) & 127;
    int wc = (ww * 8 + j + 4) & 127;
    size_t dst = ((size_t)(bb * LTOK + h * WDIM + wc)) * CDIM;
    int c = threadIdx.x;
    g_x1[dst + c] = x[dst + c] + g_proj[(size_t)wt * CDIM + c];
}

// ---------------- depthwise 3x3 conv (NHWC) + bias + GELU -------------------
// One block = 16 consecutive x pixels (same row). Thread owns 4 channels.
__global__ void __launch_bounds__(256) k_dwconv(const float* __restrict__ w9,
                                                const float* __restrict__ bconv) {
    __shared__ float wsm[HIDDIM * 9];   // 36 KB
    int tid = threadIdx.x;
    for (int e = tid; e < HIDDIM * 9; e += 256) wsm[e] = w9[e];
    __syncthreads();

    int c0 = tid * 4;
    float wr[4][9];
    #pragma unroll
    for (int q = 0; q < 4; q++)
        #pragma unroll
        for (int k = 0; k < 9; k++) wr[q][k] = wsm[(c0 + q) * 9 + k];

    float4 bia = *(const float4*)&bconv[c0];

    int p0 = blockIdx.x * 16;          // first pixel of segment (same row)
    int bb = p0 >> 14;
    int y  = (p0 >> 7) & 127;
    int x0 = p0 & 127;
    const float* base = g_h + (size_t)bb * LTOK * HIDDIM;
    float* outb = g_h2 + (size_t)bb * LTOK * HIDDIM;

    for (int px = 0; px < 16; px++) {
        int xx0 = x0 + px;
        float a0 = bia.x, a1 = bia.y, a2 = bia.z, a3 = bia.w;
        #pragma unroll
        for (int dy = -1; dy <= 1; dy++) {
            int yy = y + dy;
            if (yy < 0 || yy > 127) continue;
            #pragma unroll
            for (int dx = -1; dx <= 1; dx++) {
                int xx = xx0 + dx;
                if (xx < 0 || xx > 127) continue;
                float4 hv = *(const float4*)&base[((size_t)(yy * WDIM + xx)) * HIDDIM + c0];
                int ki = (dy + 1) * 3 + (dx + 1);
                a0 = fmaf(hv.x, wr[0][ki], a0);
                a1 = fmaf(hv.y, wr[1][ki], a1);
                a2 = fmaf(hv.z, wr[2][ki], a2);
                a3 = fmaf(hv.w, wr[3][ki], a3);
            }
        }
        float4 ov;
        ov.x = 0.5f * a0 * (1.f + erff(a0 * 0.70710678118654752f));
        ov.y = 0.5f * a1 * (1.f + erff(a1 * 0.70710678118654752f));
        ov.z = 0.5f * a2 * (1.f + erff(a2 * 0.70710678118654752f));
        ov.w = 0.5f * a3 * (1.f + erff(a3 * 0.70710678118654752f));
        *(float4*)&outb[((size_t)(y * WDIM + xx0)) * HIDDIM + c0] = ov;
    }
}

// ---------------- launch ------------------------------------------------------
extern "C" void kernel_launch(void* const* d_in, const int* in_sizes, int n_in,
                              void* d_out, int out_size) {
    const float* x       = (const float*)d_in[0];
    // d_in[1], d_in[2] are H, W scalars (128, 128) — compile-time constants here
    const float* norm1_w = (const float*)d_in[3];
    const float* norm1_b = (const float*)d_in[4];
    const float* wq      = (const float*)d_in[5];
    const float* bq      = (const float*)d_in[6];
    const float* wkv     = (const float*)d_in[7];
    const float* bkv     = (const float*)d_in[8];
    const float* rpb     = (const float*)d_in[9];
    const float* proj_w  = (const float*)d_in[10];
    const float* proj_b  = (const float*)d_in[11];
    const float* norm2_w = (const float*)d_in[12];
    const float* norm2_b = (const float*)d_in[13];
    const float* lin1_w  = (const float*)d_in[14];
    const float* lin1_b  = (const float*)d_in[15];
    const float* dw_w    = (const float*)d_in[16];
    const float* dw_b    = (const float*)d_in[17];
    const float* lin2_w  = (const float*)d_in[18];
    const float* lin2_b  = (const float*)d_in[19];
    float* out = (float*)d_out;

    float* p_xwin; cudaGetSymbolAddress((void**)&p_xwin, g_xwin);
    float* p_q;    cudaGetSymbolAddress((void**)&p_q,    g_q);
    float* p_kv;   cudaGetSymbolAddress((void**)&p_kv,   g_kv);
    float* p_o;    cudaGetSymbolAddress((void**)&p_o,    g_o);
    float* p_proj; cudaGetSymbolAddress((void**)&p_proj, g_proj);
    float* p_x1;   cudaGetSymbolAddress((void**)&p_x1,   g_x1);
    float* p_h;    cudaGetSymbolAddress((void**)&p_h,    g_h);
    float* p_h2;   cudaGetSymbolAddress((void**)&p_h2,   g_h2);

    const float scale = 0.17677669529663687f;   // 32^-0.5

    // 1) LN1 + shifted-window gather
    k_ln1_gather<<<NTOK, 256>>>(x, norm1_w, norm1_b);
    // 2) q = (xwin @ wq + bq) * scale
    k_gemm<1><<<dim3(CDIM / 128, NTOK / 128), 256>>>(p_xwin, wq, bq, p_q,
                                                     NTOK, CDIM, CDIM, scale, nullptr);
    // 3) kv = xwin @ wkv + bkv
    k_gemm<0><<<dim3(2 * CDIM / 128, NTOK / 128), 256>>>(p_xwin, wkv, bkv, p_kv,
                                                         NTOK, 2 * CDIM, CDIM, 1.f, nullptr);
    // 4) windowed attention (bias + mask + softmax + PV)
    k_attn<<<NTOK / NWIN * HEADS, 256>>>(rpb);
    // 5) proj
    k_gemm<0><<<dim3(CDIM / 128, NTOK / 128), 256>>>(p_o, proj_w, proj_b, p_proj,
                                                     NTOK, CDIM, CDIM, 1.f, nullptr);
    // 6) reverse-window/unshift scatter + residual
    k_scatter<<<NTOK, 256>>>(x);
    // 7) LN2
    k_ln2<<<NTOK, 256>>>(norm2_w, norm2_b);
    // 8) h = gelu(x2 @ lin1_w + lin1_b)
    k_gemm<2><<<dim3(HIDDIM / 128, NTOK / 128), 256>>>(p_xwin, lin1_w, lin1_b, p_h,
                                                       NTOK, HIDDIM, CDIM, 1.f, nullptr);
    // 9) depthwise conv + bias + gelu
    k_dwconv<<<NTOK / 16, 256>>>(dw_w, dw_b);
    // 10) out = x1 + h2 @ lin2_w + lin2_b
    k_gemm<3><<<dim3(CDIM / 128, NTOK / 128), 256>>>(p_h2, lin2_w, lin2_b, out,
                                                     NTOK, CDIM, HIDDIM, 1.f, p_x1);
}

// round 3
// speedup vs baseline: 1.9006x; 1.9006x over previous
#include <cuda_runtime.h>
#include <math.h>
#include <stdint.h>

// Problem constants (fixed by setup_inputs)
#define BATCH 4
#define HDIM 128
#define WDIM 128
#define CDIM 256
#define HIDDIM 1024
#define LTOK 16384              // H*W
#define NTOK 65536              // B*L
#define HEADS 8
#define HDHEAD 32

// ---------------- scratch (device globals; no allocations allowed) ----------
__device__ float g_xwin[NTOK * CDIM];          // LN output (tf32-rounded)
__device__ float g_qkv[NTOK * 3 * CDIM];       // q(scaled) | k | v, window layout
__device__ float g_o[NTOK * CDIM];             // attention output (tf32-rounded)
__device__ float g_proj[NTOK * CDIM];          // proj output (window layout)
__device__ float g_x1[NTOK * CDIM];            // residual-1 (token layout, fp32)
__device__ float g_h[NTOK * HIDDIM];           // lin1+gelu output (NHWC)
__device__ float g_h2[NTOK * HIDDIM];          // dwconv+gelu output (tf32-rounded)
// transposed weights [N][K] K-major, tf32-rounded
__device__ float g_wqkv_t[768 * 256];
__device__ float g_wproj_t[256 * 256];
__device__ float g_wlin1_t[1024 * 256];
__device__ float g_wlin2_t[256 * 1024];
__device__ float g_bqkv[768];

// ============================ helpers ========================================
__device__ __forceinline__ float tf32r(float x) {
    uint32_t u;
    asm("cvt.rna.tf32.f32 %0, %1;" : "=r"(u) : "f"(x));
    return __uint_as_float(u);
}

#define CP_ASYNC16(saddr, gptr) \
    asm volatile("cp.async.cg.shared.global [%0], [%1], 16;" \
        :: "r"((uint32_t)(saddr)), "l"(gptr) : "memory")
#define CP_COMMIT() asm volatile("cp.async.commit_group;" ::: "memory")
#define CP_WAIT1()  asm volatile("cp.async.wait_group 1;" ::: "memory")
#define CP_WAIT0()  asm volatile("cp.async.wait_group 0;" ::: "memory")

__device__ __forceinline__ uint32_t smem_u32(const void* p) {
    uint32_t a;
    asm("{ .reg .u64 t; cvta.to.shared.u64 t, %1; cvt.u32.u64 %0, t; }"
        : "=r"(a) : "l"(p));
    return a;
}

// ============================ weight prep ====================================
__global__ void k_prep_qkvw(const float* __restrict__ wq, const float* __restrict__ wkv,
                            const float* __restrict__ bq, const float* __restrict__ bkv) {
    int n = blockIdx.x;          // 0..767
    int k = threadIdx.x;         // 0..255
    float v = (n < 256) ? wq[k * 256 + n] : wkv[k * 512 + (n - 256)];
    g_wqkv_t[n * 256 + k] = tf32r(v);
    if (k == 0) g_bqkv[n] = (n < 256) ? bq[n] : bkv[n - 256];
}

__global__ void k_transpose(const float* __restrict__ in, float* __restrict__ out,
                            int N, int K) {
    int n = blockIdx.x;
    for (int k = threadIdx.x; k < K; k += blockDim.x)
        out[(size_t)n * K + k] = tf32r(in[(size_t)k * N + n]);
}

// ---------------- LN1 + shifted-window gather --------------------------------
__global__ void k_ln1_gather(const float* __restrict__ x,
                             const float* __restrict__ w,
                             const float* __restrict__ b) {
    int wt  = blockIdx.x;
    int bb  = wt >> 14;
    int rem = wt & 16383;
    int win = rem >> 6, n = rem & 63;
    int wh = win >> 4, ww = win & 15;
    int i = n >> 3, j = n & 7;
    int h  = (wh * 8 + i + 4) & 127;
    int wc = (ww * 8 + j + 4) & 127;
    const float* src = x + ((size_t)(bb * LTOK + h * WDIM + wc)) * CDIM;
    int c = threadIdx.x;
    float v = src[c];
    float s = v, s2 = v * v;
    #pragma unroll
    for (int o = 16; o > 0; o >>= 1) {
        s  += __shfl_down_sync(0xffffffffu, s, o);
        s2 += __shfl_down_sync(0xffffffffu, s2, o);
    }
    __shared__ float sm[8], sm2[8];
    __shared__ float mean_s, rstd_s;
    if ((c & 31) == 0) { sm[c >> 5] = s; sm2[c >> 5] = s2; }
    __syncthreads();
    if (c == 0) {
        float ts = 0.f, ts2 = 0.f;
        #pragma unroll
        for (int k2 = 0; k2 < 8; k2++) { ts += sm[k2]; ts2 += sm2[k2]; }
        float m   = ts * (1.f / 256.f);
        float var = ts2 * (1.f / 256.f) - m * m;
        mean_s = m;
        rstd_s = rsqrtf(var + 1e-5f);
    }
    __syncthreads();
    g_xwin[(size_t)wt * CDIM + c] = tf32r((v - mean_s) * rstd_s * w[c] + b[c]);
}

// ---------------- reverse window + unshift + residual + LN2 (fused) ----------
__global__ void k_scatter_ln2(const float* __restrict__ x,
                              const float* __restrict__ w, const float* __restrict__ b) {
    int wt  = blockIdx.x;
    int bb  = wt >> 14;
    int rem = wt & 16383;
    int win = rem >> 6, n = rem & 63;
    int wh = win >> 4, ww = win & 15;
    int i = n >> 3, j = n & 7;
    int h  = (wh * 8 + i + 4) & 127;
    int wc = (ww * 8 + j + 4) & 127;
    size_t dst = ((size_t)(bb * LTOK + h * WDIM + wc)) * CDIM;
    int c = threadIdx.x;
    float v = x[dst + c] + g_proj[(size_t)wt * CDIM + c];
    g_x1[dst + c] = v;
    float s = v, s2 = v * v;
    #pragma unroll
    for (int o = 16; o > 0; o >>= 1) {
        s  += __shfl_down_sync(0xffffffffu, s, o);
        s2 += __shfl_down_sync(0xffffffffu, s2, o);
    }
    __shared__ float sm[8], sm2[8];
    __shared__ float mean_s, rstd_s;
    if ((c & 31) == 0) { sm[c >> 5] = s; sm2[c >> 5] = s2; }
    __syncthreads();
    if (c == 0) {
        float ts = 0.f, ts2 = 0.f;
        #pragma unroll
        for (int k2 = 0; k2 < 8; k2++) { ts += sm[k2]; ts2 += sm2[k2]; }
        float m   = ts * (1.f / 256.f);
        float var = ts2 * (1.f / 256.f) - m * m;
        mean_s = m;
        rstd_s = rsqrtf(var + 1e-5f);
    }
    __syncthreads();
    g_xwin[dst + c] = tf32r((v - mean_s) * rstd_s * w[c] + b[c]);
}

// ================ tf32 mma.sync GEMM: C[M,Ntot] = A[M,K] @ Bt[Ntot,K]^T ======
// CTA tile 128x128, 256 threads (2x4 warps, warp tile 64x32).
// Double-buffered cp.async, K-chunk 16. smem pitch 20 floats (conflict-free).
// EPI: 0=+bias; 1=(+bias)*scale for cols<256; 2=gelu(+bias); 3=+bias+res
#define PITCH 20
#define STG_F (128 * PITCH)            // floats per stage
#define SMEM_GEMM_TOTAL (4 * STG_F * 4)  // 2 stages A + 2 stages B, bytes

__device__ __forceinline__ void load_stage(uint32_t sb, int s,
                                           const float* __restrict__ Ab,
                                           const float* __restrict__ Bb,
                                           int K, int kc, int tid) {
    const float* Ag = Ab + kc * 16;
    const float* Bg = Bb + kc * 16;
    uint32_t abase = sb + s * (STG_F * 4);
    uint32_t bbase = sb + 2 * (STG_F * 4) + s * (STG_F * 4);
    #pragma unroll
    for (int i = 0; i < 2; i++) {
        int u = tid + (i << 8);
        int row = u >> 2, seg = u & 3;
        uint32_t off = (row * PITCH + seg * 4) * 4;
        CP_ASYNC16(abase + off, Ag + (size_t)row * K + seg * 4);
        CP_ASYNC16(bbase + off, Bg + (size_t)row * K + seg * 4);
    }
    CP_COMMIT();
}

template <int EPI>
__global__ void __launch_bounds__(256, 2) k_gemm_mma(
    const float* __restrict__ A, const float* __restrict__ Bt,
    const float* __restrict__ bias, float* __restrict__ C,
    int K, int Ntot, float scale, const float* __restrict__ res)
{
    extern __shared__ char smem[];
    uint32_t sb = smem_u32(smem);
    const float* As = (const float*)smem;
    const float* Bs = (const float*)(smem + 2 * STG_F * 4);

    int tid = threadIdx.x, lane = tid & 31, wid = tid >> 5;
    int wm = wid >> 2, wn = wid & 3;        // 2 x 4 warp grid
    int gid = lane >> 2, tg = lane & 3;
    int bm = blockIdx.y << 7, bn = blockIdx.x << 7;
    const float* Ab = A + (size_t)bm * K;
    const float* Bb = Bt + (size_t)bn * K;
    int nKC = K >> 4;

    float acc[4][4][4];
    #pragma unroll
    for (int mt = 0; mt < 4; mt++)
        #pragma unroll
        for (int nt = 0; nt < 4; nt++)
            #pragma unroll
            for (int q = 0; q < 4; q++) acc[mt][nt][q] = 0.f;

    load_stage(sb, 0, Ab, Bb, K, 0, tid);

    for (int kc = 0; kc < nKC; kc++) {
        if (kc + 1 < nKC) {
            load_stage(sb, (kc + 1) & 1, Ab, Bb, K, kc + 1, tid);
            CP_WAIT1();
        } else {
            CP_WAIT0();
        }
        __syncthreads();
        const float* Asp = As + (kc & 1) * STG_F;
        const float* Bsp = Bs + (kc & 1) * STG_F;
        #pragma unroll
        for (int k8 = 0; k8 < 16; k8 += 8) {
            uint32_t a[4][4], b[4][2];
            #pragma unroll
            for (int mt = 0; mt < 4; mt++) {
                int r = wm * 64 + mt * 16 + gid;
                a[mt][0] = __float_as_uint(Asp[r * PITCH + k8 + tg]);
                a[mt][1] = __float_as_uint(Asp[(r + 8) * PITCH + k8 + tg]);
                a[mt][2] = __float_as_uint(Asp[r * PITCH + k8 + tg + 4]);
                a[mt][3] = __float_as_uint(Asp[(r + 8) * PITCH + k8 + tg + 4]);
            }
            #pragma unroll
            for (int nt = 0; nt < 4; nt++) {
                int n = wn * 32 + nt * 8 + gid;
                b[nt][0] = __float_as_uint(Bsp[n * PITCH + k8 + tg]);
                b[nt][1] = __float_as_uint(Bsp[n * PITCH + k8 + tg + 4]);
            }
            #pragma unroll
            for (int mt = 0; mt < 4; mt++)
                #pragma unroll
                for (int nt = 0; nt < 4; nt++) {
                    asm volatile(
                        "mma.sync.aligned.m16n8k8.row.col.f32.tf32.tf32.f32 "
                        "{%0,%1,%2,%3}, {%4,%5,%6,%7}, {%8,%9}, {%0,%1,%2,%3};"
                        : "+f"(acc[mt][nt][0]), "+f"(acc[mt][nt][1]),
                          "+f"(acc[mt][nt][2]), "+f"(acc[mt][nt][3])
                        : "r"(a[mt][0]), "r"(a[mt][1]), "r"(a[mt][2]), "r"(a[mt][3]),
                          "r"(b[nt][0]), "r"(b[nt][1]));
                }
        }
        __syncthreads();
    }

    // epilogue: c0/c1 -> (row, col*2..+1); c2/c3 -> (row+8, ...)
    #pragma unroll
    for (int mt = 0; mt < 4; mt++) {
        int r0 = bm + wm * 64 + mt * 16 + gid;
        int r1 = r0 + 8;
        #pragma unroll
        for (int nt = 0; nt < 4; nt++) {
            int c0 = bn + wn * 32 + nt * 8 + tg * 2;
            float2 b2 = *(const float2*)&bias[c0];
            float v00 = acc[mt][nt][0] + b2.x;
            float v01 = acc[mt][nt][1] + b2.y;
            float v10 = acc[mt][nt][2] + b2.x;
            float v11 = acc[mt][nt][3] + b2.y;
            if (EPI == 1) {
                if (c0 < 256) { v00 *= scale; v01 *= scale; v10 *= scale; v11 *= scale; }
            }
            if (EPI == 2) {
                v00 = 0.5f * v00 * (1.f + erff(v00 * 0.70710678118654752f));
                v01 = 0.5f * v01 * (1.f + erff(v01 * 0.70710678118654752f));
                v10 = 0.5f * v10 * (1.f + erff(v10 * 0.70710678118654752f));
                v11 = 0.5f * v11 * (1.f + erff(v11 * 0.70710678118654752f));
            }
            if (EPI == 3) {
                float2 ra = *(const float2*)&res[(size_t)r0 * Ntot + c0];
                float2 rb = *(const float2*)&res[(size_t)r1 * Ntot + c0];
                v00 += ra.x; v01 += ra.y; v10 += rb.x; v11 += rb.y;
            }
            float2 oa; oa.x = v00; oa.y = v01;
            float2 ob; ob.x = v10; ob.y = v11;
            *(float2*)&C[(size_t)r0 * Ntot + c0] = oa;
            *(float2*)&C[(size_t)r1 * Ntot + c0] = ob;
        }
    }
}

// ---------------- fused windowed attention ----------------------------------
__global__ void __launch_bounds__(256) k_attn(const float* __restrict__ rpb) {
    int blk   = blockIdx.x;
    int head  = blk & 7;
    int wglob = blk >> 3;
    int win   = wglob & 255;
    int wh = win >> 4, ww = win & 15;
    int wt0 = wglob << 6;

    __shared__ float qs[64][36], ks[64][36], vs[64][36];
    __shared__ float at[64][65];

    int tid = threadIdx.x;
    const float* base = g_qkv + (size_t)wt0 * 768 + head * HDHEAD;
    for (int e = tid; e < 2048; e += 256) {
        int n = e >> 5, d = e & 31;
        const float* rowp = base + (size_t)n * 768;
        qs[n][d] = rowp[d];
        ks[n][d] = rowp[256 + d];
        vs[n][d] = rowp[512 + d];
    }
    __syncthreads();

    int r = tid >> 2, cg = tid & 3;
    int ir = r >> 3, jr = r & 7;
    float qr[32];
    #pragma unroll
    for (int d4 = 0; d4 < 8; d4++) {
        float4 t = *(const float4*)&qs[r][d4 * 4];
        qr[d4 * 4 + 0] = t.x; qr[d4 * 4 + 1] = t.y;
        qr[d4 * 4 + 2] = t.z; qr[d4 * 4 + 3] = t.w;
    }
    int regr = ((wh == 15) ? (ir < 4 ? 1 : 2) : 0) * 3 +
               ((ww == 15) ? (jr < 4 ? 1 : 2) : 0);

    float av[16];
    float mx = -1e30f;
    #pragma unroll
    for (int cc = 0; cc < 16; cc++) {
        int c = cg * 16 + cc;
        float s = 0.f;
        #pragma unroll
        for (int d4 = 0; d4 < 8; d4++) {
            float4 kk = *(const float4*)&ks[c][d4 * 4];
            s = fmaf(qr[d4 * 4 + 0], kk.x, s);
            s = fmaf(qr[d4 * 4 + 1], kk.y, s);
            s = fmaf(qr[d4 * 4 + 2], kk.z, s);
            s = fmaf(qr[d4 * 4 + 3], kk.w, s);
        }
        int ic = c >> 3, jc = c & 7;
        s += __ldg(&rpb[((ir - ic + 7) * 15 + (jr - jc + 7)) * HEADS + head]);
        int regc = ((wh == 15) ? (ic < 4 ? 1 : 2) : 0) * 3 +
                   ((ww == 15) ? (jc < 4 ? 1 : 2) : 0);
        if (regc != regr) s -= 100.f;
        av[cc] = s;
        mx = fmaxf(mx, s);
    }
    mx = fmaxf(mx, __shfl_xor_sync(0xffffffffu, mx, 1));
    mx = fmaxf(mx, __shfl_xor_sync(0xffffffffu, mx, 2));
    float sum = 0.f;
    #pragma unroll
    for (int cc = 0; cc < 16; cc++) { av[cc] = expf(av[cc] - mx); sum += av[cc]; }
    sum += __shfl_xor_sync(0xffffffffu, sum, 1);
    sum += __shfl_xor_sync(0xffffffffu, sum, 2);
    float inv = 1.f / sum;
    #pragma unroll
    for (int cc = 0; cc < 16; cc++) at[r][cg * 16 + cc] = av[cc] * inv;
    __syncthreads();

    float4 o0 = {0.f, 0.f, 0.f, 0.f}, o1 = {0.f, 0.f, 0.f, 0.f};
    #pragma unroll
    for (int m = 0; m < 64; m++) {
        float a = at[r][m];
        float4 va = *(const float4*)&vs[m][cg * 8];
        float4 vb = *(const float4*)&vs[m][cg * 8 + 4];
        o0.x = fmaf(a, va.x, o0.x); o0.y = fmaf(a, va.y, o0.y);
        o0.z = fmaf(a, va.z, o0.z); o0.w = fmaf(a, va.w, o0.w);
        o1.x = fmaf(a, vb.x, o1.x); o1.y = fmaf(a, vb.y, o1.y);
        o1.z = fmaf(a, vb.z, o1.z); o1.w = fmaf(a, vb.w, o1.w);
    }
    // tf32-round attention output (feeds proj GEMM)
    o0.x = tf32r(o0.x); o0.y = tf32r(o0.y); o0.z = tf32r(o0.z); o0.w = tf32r(o0.w);
    o1.x = tf32r(o1.x); o1.y = tf32r(o1.y); o1.z = tf32r(o1.z); o1.w = tf32r(o1.w);
    float* op = &g_o[(size_t)(wt0 + r) * CDIM + head * HDHEAD + cg * 8];
    *(float4*)op       = o0;
    *(float4*)(op + 4) = o1;
}

// ---------------- depthwise 3x3 conv (NHWC) + bias + GELU -------------------
__global__ void __launch_bounds__(256) k_dwconv(const float* __restrict__ w9,
                                                const float* __restrict__ bconv) {
    __shared__ float wsm[HIDDIM * 9];
    int tid = threadIdx.x;
    for (int e = tid; e < HIDDIM * 9; e += 256) wsm[e] = w9[e];
    __syncthreads();

    int c0 = tid * 4;
    float wr[4][9];
    #pragma unroll
    for (int q = 0; q < 4; q++)
        #pragma unroll
        for (int k = 0; k < 9; k++) wr[q][k] = wsm[(c0 + q) * 9 + k];

    float4 bia = *(const float4*)&bconv[c0];

    int p0 = blockIdx.x * 16;
    int bb = p0 >> 14;
    int y  = (p0 >> 7) & 127;
    int x0 = p0 & 127;
    const float* base = g_h + (size_t)bb * LTOK * HIDDIM;
    float* outb = g_h2 + (size_t)bb * LTOK * HIDDIM;

    for (int px = 0; px < 16; px++) {
        int xx0 = x0 + px;
        float a0 = bia.x, a1 = bia.y, a2 = bia.z, a3 = bia.w;
        #pragma unroll
        for (int dy = -1; dy <= 1; dy++) {
            int yy = y + dy;
            if (yy < 0 || yy > 127) continue;
            #pragma unroll
            for (int dx = -1; dx <= 1; dx++) {
                int xx = xx0 + dx;
                if (xx < 0 || xx > 127) continue;
                float4 hv = *(const float4*)&base[((size_t)(yy * WDIM + xx)) * HIDDIM + c0];
                int ki = (dy + 1) * 3 + (dx + 1);
                a0 = fmaf(hv.x, wr[0][ki], a0);
                a1 = fmaf(hv.y, wr[1][ki], a1);
                a2 = fmaf(hv.z, wr[2][ki], a2);
                a3 = fmaf(hv.w, wr[3][ki], a3);
            }
        }
        float4 ov;
        ov.x = tf32r(0.5f * a0 * (1.f + erff(a0 * 0.70710678118654752f)));
        ov.y = tf32r(0.5f * a1 * (1.f + erff(a1 * 0.70710678118654752f)));
        ov.z = tf32r(0.5f * a2 * (1.f + erff(a2 * 0.70710678118654752f)));
        ov.w = tf32r(0.5f * a3 * (1.f + erff(a3 * 0.70710678118654752f)));
        *(float4*)&outb[((size_t)(y * WDIM + xx0)) * HIDDIM + c0] = ov;
    }
}

// ---------------- launch -----------------------------------------------------
extern "C" void kernel_launch(void* const* d_in, const int* in_sizes, int n_in,
                              void* d_out, int out_size) {
    const float* x       = (const float*)d_in[0];
    const float* norm1_w = (const float*)d_in[3];
    const float* norm1_b = (const float*)d_in[4];
    const float* wq      = (const float*)d_in[5];
    const float* bq      = (const float*)d_in[6];
    const float* wkv     = (const float*)d_in[7];
    const float* bkv     = (const float*)d_in[8];
    const float* rpb     = (const float*)d_in[9];
    const float* proj_w  = (const float*)d_in[10];
    const float* proj_b  = (const float*)d_in[11];
    const float* norm2_w = (const float*)d_in[12];
    const float* norm2_b = (const float*)d_in[13];
    const float* lin1_w  = (const float*)d_in[14];
    const float* lin1_b  = (const float*)d_in[15];
    const float* dw_w    = (const float*)d_in[16];
    const float* dw_b    = (const float*)d_in[17];
    const float* lin2_w  = (const float*)d_in[18];
    const float* lin2_b  = (const float*)d_in[19];
    float* out = (float*)d_out;

    float* p_xwin;  cudaGetSymbolAddress((void**)&p_xwin,  g_xwin);
    float* p_qkv;   cudaGetSymbolAddress((void**)&p_qkv,   g_qkv);
    float* p_o;     cudaGetSymbolAddress((void**)&p_o,     g_o);
    float* p_proj;  cudaGetSymbolAddress((void**)&p_proj,  g_proj);
    float* p_x1;    cudaGetSymbolAddress((void**)&p_x1,    g_x1);
    float* p_h;     cudaGetSymbolAddress((void**)&p_h,     g_h);
    float* p_h2;    cudaGetSymbolAddress((void**)&p_h2,    g_h2);
    float* p_wqkv;  cudaGetSymbolAddress((void**)&p_wqkv,  g_wqkv_t);
    float* p_wproj; cudaGetSymbolAddress((void**)&p_wproj, g_wproj_t);
    float* p_wl1;   cudaGetSymbolAddress((void**)&p_wl1,   g_wlin1_t);
    float* p_wl2;   cudaGetSymbolAddress((void**)&p_wl2,   g_wlin2_t);
    float* p_bqkv;  cudaGetSymbolAddress((void**)&p_bqkv,  g_bqkv);

    const float scale = 0.17677669529663687f;   // 32^-0.5

    // weight prep (transposed, K-major, tf32-rounded)
    k_prep_qkvw<<<768, 256>>>(wq, wkv, bq, bkv);
    k_transpose<<<256, 256>>>(proj_w, p_wproj, 256, 256);
    k_transpose<<<1024, 256>>>(lin1_w, p_wl1, 1024, 256);
    k_transpose<<<256, 256>>>(lin2_w, p_wl2, 256, 1024);

    // 1) LN1 + shifted-window gather
    k_ln1_gather<<<NTOK, 256>>>(x, norm1_w, norm1_b);
    // 2) qkv = xwin @ [wq|wkv] + [bq|bkv], q scaled
    k_gemm_mma<1><<<dim3(6, NTOK / 128), 256, SMEM_GEMM_TOTAL>>>(
        p_xwin, p_wqkv, p_bqkv, p_qkv, 256, 768, scale, nullptr);
    // 3) windowed attention
    k_attn<<<(NTOK / 64) * HEADS, 256>>>(rpb);
    // 4) proj
    k_gemm_mma<0><<<dim3(2, NTOK / 128), 256, SMEM_GEMM_TOTAL>>>(
        p_o, p_wproj, proj_b, p_proj, 256, 256, 1.f, nullptr);
    // 5) reverse-window scatter + residual + LN2 (fused)
    k_scatter_ln2<<<NTOK, 256>>>(x, norm2_w, norm2_b);
    // 6) h = gelu(x2 @ lin1_w + lin1_b)
    k_gemm_mma<2><<<dim3(8, NTOK / 128), 256, SMEM_GEMM_TOTAL>>>(
        p_xwin, p_wl1, lin1_b, p_h, 256, 1024, 1.f, nullptr);
    // 7) depthwise conv + bias + gelu
    k_dwconv<<<NTOK / 16, 256>>>(dw_w, dw_b);
    // 8) out = x1 + h2 @ lin2_w + lin2_b
    k_gemm_mma<3><<<dim3(2, NTOK / 128), 256, SMEM_GEMM_TOTAL>>>(
        p_h2, p_wl2, lin2_b, out, 1024, 256, 1.f, p_x1);
}

// round 4
// speedup vs baseline: 2.5175x; 1.3246x over previous
#include <cuda_runtime.h>
#include <cuda_bf16.h>
#include <math.h>
#include <stdint.h>

#define BATCH 4
#define HDIM 128
#define WDIM 128
#define CDIM 256
#define HIDDIM 1024
#define LTOK 16384
#define NTOK 65536
#define HEADS 8
#define HDHEAD 32

// ---------------- scratch ----------------------------------------------------
__device__ __nv_bfloat16 g_xwin[NTOK * CDIM];     // LN output (bf16)
__device__ __nv_bfloat16 g_qkv[NTOK * 3 * CDIM];  // q(scaled)|k|v (bf16)
__device__ __nv_bfloat16 g_o[NTOK * CDIM];        // attn out (bf16)
__device__ float         g_proj[NTOK * CDIM];     // proj out (fp32)
__device__ float         g_x1[NTOK * CDIM];       // residual-1 (fp32)
__device__ __nv_bfloat16 g_h[NTOK * HIDDIM];      // lin1+gelu (bf16)
__device__ __nv_bfloat16 g_h2[NTOK * HIDDIM];     // dwconv+gelu (bf16)
__device__ __nv_bfloat16 g_wqkv_t[768 * 256];     // [N][K] K-major bf16
__device__ __nv_bfloat16 g_wproj_t[256 * 256];
__device__ __nv_bfloat16 g_wlin1_t[1024 * 256];
__device__ __nv_bfloat16 g_wlin2_t[256 * 1024];
__device__ float         g_bqkv[768];

// ---------------- helpers ----------------------------------------------------
__device__ __forceinline__ uint32_t smem_u32(const void* p) {
    uint32_t a;
    asm("{ .reg .u64 t; cvta.to.shared.u64 t, %1; cvt.u32.u64 %0, t; }"
        : "=r"(a) : "l"(p));
    return a;
}
__device__ __forceinline__ uint32_t pack_bf16x2(float lo, float hi) {
    uint32_t u;
    asm("cvt.rn.bf16x2.f32 %0, %1, %2;" : "=r"(u) : "f"(hi), "f"(lo));
    return u;
}
__device__ __forceinline__ float bflo(uint32_t u) { return __uint_as_float(u << 16); }
__device__ __forceinline__ float bfhi(uint32_t u) { return __uint_as_float(u & 0xffff0000u); }

#define CP_ASYNC16(saddr, gptr) \
    asm volatile("cp.async.cg.shared.global [%0], [%1], 16;" \
        :: "r"((uint32_t)(saddr)), "l"(gptr) : "memory")
#define CP_COMMIT() asm volatile("cp.async.commit_group;" ::: "memory")
#define CP_WAIT_2() asm volatile("cp.async.wait_group 2;" ::: "memory")
#define CP_WAIT_1() asm volatile("cp.async.wait_group 1;" ::: "memory")
#define CP_WAIT_0() asm volatile("cp.async.wait_group 0;" ::: "memory")

#define LDMATRIX_X4(r0, r1, r2, r3, addr) \
    asm volatile("ldmatrix.sync.aligned.m8n8.x4.shared.b16 {%0,%1,%2,%3}, [%4];" \
        : "=r"(r0), "=r"(r1), "=r"(r2), "=r"(r3) : "r"(addr))

#define MMA_BF16(c, a0, a1, a2, a3, b0, b1) \
    asm volatile("mma.sync.aligned.m16n8k16.row.col.f32.bf16.bf16.f32 " \
        "{%0,%1,%2,%3},{%4,%5,%6,%7},{%8,%9},{%0,%1,%2,%3};" \
        : "+f"((c)[0]), "+f"((c)[1]), "+f"((c)[2]), "+f"((c)[3]) \
        : "r"(a0), "r"(a1), "r"(a2), "r"(a3), "r"(b0), "r"(b1))

// ---------------- weight prep -------------------------------------------------
__global__ void k_prep_qkvw(const float* __restrict__ wq, const float* __restrict__ wkv,
                            const float* __restrict__ bq, const float* __restrict__ bkv) {
    int n = blockIdx.x, k = threadIdx.x;
    float v = (n < 256) ? wq[k * 256 + n] : wkv[k * 512 + (n - 256)];
    g_wqkv_t[n * 256 + k] = __float2bfloat16_rn(v);
    if (k == 0) g_bqkv[n] = (n < 256) ? bq[n] : bkv[n - 256];
}
__global__ void k_transpose(const float* __restrict__ in, __nv_bfloat16* __restrict__ out,
                            int N, int K) {
    int n = blockIdx.x;
    for (int k = threadIdx.x; k < K; k += blockDim.x)
        out[(size_t)n * K + k] = __float2bfloat16_rn(in[(size_t)k * N + n]);
}

// ---------------- LN1 + shifted-window gather ---------------------------------
__global__ void k_ln1_gather(const float* __restrict__ x,
                             const float* __restrict__ w, const float* __restrict__ b) {
    int wt = blockIdx.x;
    int bb = wt >> 14, rem = wt & 16383;
    int win = rem >> 6, n = rem & 63;
    int wh = win >> 4, ww = win & 15;
    int i = n >> 3, j = n & 7;
    int h = (wh * 8 + i + 4) & 127, wc = (ww * 8 + j + 4) & 127;
    const float* src = x + ((size_t)(bb * LTOK + h * WDIM + wc)) * CDIM;
    int c = threadIdx.x;
    float v = src[c];
    float s = v, s2 = v * v;
    #pragma unroll
    for (int o = 16; o > 0; o >>= 1) {
        s  += __shfl_down_sync(0xffffffffu, s, o);
        s2 += __shfl_down_sync(0xffffffffu, s2, o);
    }
    __shared__ float sm[8], sm2[8];
    __shared__ float mean_s, rstd_s;
    if ((c & 31) == 0) { sm[c >> 5] = s; sm2[c >> 5] = s2; }
    __syncthreads();
    if (c == 0) {
        float ts = 0.f, ts2 = 0.f;
        #pragma unroll
        for (int k2 = 0; k2 < 8; k2++) { ts += sm[k2]; ts2 += sm2[k2]; }
        float m = ts * (1.f / 256.f);
        mean_s = m;
        rstd_s = rsqrtf(ts2 * (1.f / 256.f) - m * m + 1e-5f);
    }
    __syncthreads();
    g_xwin[(size_t)wt * CDIM + c] = __float2bfloat16_rn((v - mean_s) * rstd_s * w[c] + b[c]);
}

// ---------------- reverse window + residual + LN2 (fused) ---------------------
__global__ void k_scatter_ln2(const float* __restrict__ x,
                              const float* __restrict__ w, const float* __restrict__ b) {
    int wt = blockIdx.x;
    int bb = wt >> 14, rem = wt & 16383;
    int win = rem >> 6, n = rem & 63;
    int wh = win >> 4, ww = win & 15;
    int i = n >> 3, j = n & 7;
    int h = (wh * 8 + i + 4) & 127, wc = (ww * 8 + j + 4) & 127;
    size_t dst = ((size_t)(bb * LTOK + h * WDIM + wc)) * CDIM;
    int c = threadIdx.x;
    float v = x[dst + c] + g_proj[(size_t)wt * CDIM + c];
    g_x1[dst + c] = v;
    float s = v, s2 = v * v;
    #pragma unroll
    for (int o = 16; o > 0; o >>= 1) {
        s  += __shfl_down_sync(0xffffffffu, s, o);
        s2 += __shfl_down_sync(0xffffffffu, s2, o);
    }
    __shared__ float sm[8], sm2[8];
    __shared__ float mean_s, rstd_s;
    if ((c & 31) == 0) { sm[c >> 5] = s; sm2[c >> 5] = s2; }
    __syncthreads();
    if (c == 0) {
        float ts = 0.f, ts2 = 0.f;
        #pragma unroll
        for (int k2 = 0; k2 < 8; k2++) { ts += sm[k2]; ts2 += sm2[k2]; }
        float m = ts * (1.f / 256.f);
        mean_s = m;
        rstd_s = rsqrtf(ts2 * (1.f / 256.f) - m * m + 1e-5f);
    }
    __syncthreads();
    g_xwin[dst + c] = __float2bfloat16_rn((v - mean_s) * rstd_s * w[c] + b[c]);
}

// ============ bf16 mma GEMM: C[M,Ntot] = A[M,K] @ Bt[Ntot,K]^T ================
// CTA 128x128, 256 thr (2x4 warps, warp tile 64x32). 3-stage cp.async, K-chunk 32.
// smem row = 32 bf16 = 64B = 4 chunks of 16B, swizzle chunk' = chunk ^ ((row>>1)&3).
// EPI: 0 = fp32 +bias; 1 = bf16 (+bias)*scale for col<256; 2 = bf16 gelu(+bias);
//      3 = fp32 +bias+res
#define STAGE_B 8192

__device__ __forceinline__ void load_stage_bf(uint32_t sb, int s,
                                              const __nv_bfloat16* __restrict__ Ab,
                                              const __nv_bfloat16* __restrict__ Bb,
                                              int K, int kc, int tid) {
    const __nv_bfloat16* Ag = Ab + kc * 32;
    const __nv_bfloat16* Bg = Bb + kc * 32;
    uint32_t abase = sb + s * STAGE_B;
    uint32_t bbase = sb + 3 * STAGE_B + s * STAGE_B;
    #pragma unroll
    for (int i = 0; i < 2; i++) {
        int idx = tid + (i << 8);
        int row = idx >> 2, ch = idx & 3;
        int sw = ch ^ ((row >> 1) & 3);
        CP_ASYNC16(abase + row * 64 + sw * 16, Ag + (size_t)row * K + ch * 8);
        CP_ASYNC16(bbase + row * 64 + sw * 16, Bg + (size_t)row * K + ch * 8);
    }
    CP_COMMIT();
}

template <int EPI>
__global__ void __launch_bounds__(256) k_gemm_bf16(
    const __nv_bfloat16* __restrict__ A, const __nv_bfloat16* __restrict__ Bt,
    const float* __restrict__ bias, void* __restrict__ Cout,
    int K, int Ntot, float scale, const float* __restrict__ res)
{
    __shared__ __align__(16) char smem[6 * STAGE_B];   // 48KB: 3 A stages + 3 B stages
    uint32_t sb = smem_u32(smem);

    int tid = threadIdx.x, lane = tid & 31, wid = tid >> 5;
    int wm = wid >> 2, wn = wid & 3;
    int bm = blockIdx.y << 7, bn = blockIdx.x << 7;
    const __nv_bfloat16* Ab = A + (size_t)bm * K;
    const __nv_bfloat16* Bb = Bt + (size_t)bn * K;
    int nKC = K >> 5;

    // lane-constant ldmatrix offsets
    int rA = (lane & 7) + ((lane >> 3) & 1) * 8;   // row within 16-row tile
    int cA = lane >> 4;                            // chunk low bit
    int selA = (rA >> 1) & 3;
    uint32_t aRowOff = (uint32_t)(wm * 64 + rA) * 64;
    uint32_t aChunkOff[2] = { (uint32_t)((0 + cA) ^ selA) * 16,
                              (uint32_t)((2 + cA) ^ selA) * 16 };
    int rB = lane & 7, cB = lane >> 3;
    int selB = (rB >> 1) & 3;
    uint32_t bOff = (uint32_t)(wn * 32 + rB) * 64 + (uint32_t)(cB ^ selB) * 16;

    float acc[4][4][4];
    #pragma unroll
    for (int mt = 0; mt < 4; mt++)
        #pragma unroll
        for (int nt = 0; nt < 4; nt++)
            #pragma unroll
            for (int q = 0; q < 4; q++) acc[mt][nt][q] = 0.f;

    load_stage_bf(sb, 0, Ab, Bb, K, 0, tid);
    if (nKC > 1) load_stage_bf(sb, 1, Ab, Bb, K, 1, tid);
    else CP_COMMIT();

    for (int kc = 0; kc < nKC; kc++) {
        if (kc + 2 < nKC) { load_stage_bf(sb, (kc + 2) % 3, Ab, Bb, K, kc + 2, tid); CP_WAIT_2(); }
        else if (kc + 1 < nKC) { CP_WAIT_1(); }
        else { CP_WAIT_0(); }
        __syncthreads();

        uint32_t asp = sb + (kc % 3) * STAGE_B;
        uint32_t bsp = sb + 3 * STAGE_B + (kc % 3) * STAGE_B;

        uint32_t bfr[4][4];
        #pragma unroll
        for (int nt = 0; nt < 4; nt++)
            LDMATRIX_X4(bfr[nt][0], bfr[nt][1], bfr[nt][2], bfr[nt][3],
                        bsp + bOff + nt * 512);
        #pragma unroll
        for (int kk = 0; kk < 2; kk++) {
            #pragma unroll
            for (int mt = 0; mt < 4; mt++) {
                uint32_t a0, a1, a2, a3;
                LDMATRIX_X4(a0, a1, a2, a3, asp + aRowOff + mt * 1024 + aChunkOff[kk]);
                #pragma unroll
                for (int nt = 0; nt < 4; nt++)
                    MMA_BF16(acc[mt][nt], a0, a1, a2, a3,
                             bfr[nt][kk * 2], bfr[nt][kk * 2 + 1]);
            }
        }
        __syncthreads();
    }

    int g = lane >> 2, t = lane & 3;
    #pragma unroll
    for (int mt = 0; mt < 4; mt++) {
        int r0 = bm + wm * 64 + mt * 16 + g;
        int r1 = r0 + 8;
        #pragma unroll
        for (int nt = 0; nt < 4; nt++) {
            int c0 = bn + wn * 32 + nt * 8 + t * 2;
            float2 b2 = *(const float2*)&bias[c0];
            float v00 = acc[mt][nt][0] + b2.x;
            float v01 = acc[mt][nt][1] + b2.y;
            float v10 = acc[mt][nt][2] + b2.x;
            float v11 = acc[mt][nt][3] + b2.y;
            if (EPI == 1) {
                if (c0 < 256) { v00 *= scale; v01 *= scale; v10 *= scale; v11 *= scale; }
            }
            if (EPI == 2) {
                v00 = 0.5f * v00 * (1.f + erff(v00 * 0.70710678118654752f));
                v01 = 0.5f * v01 * (1.f + erff(v01 * 0.70710678118654752f));
                v10 = 0.5f * v10 * (1.f + erff(v10 * 0.70710678118654752f));
                v11 = 0.5f * v11 * (1.f + erff(v11 * 0.70710678118654752f));
            }
            if (EPI == 3) {
                float2 ra = *(const float2*)&res[(size_t)r0 * Ntot + c0];
                float2 rb = *(const float2*)&res[(size_t)r1 * Ntot + c0];
                v00 += ra.x; v01 += ra.y; v10 += rb.x; v11 += rb.y;
            }
            if (EPI == 0 || EPI == 3) {
                float* C = (float*)Cout;
                float2 oa; oa.x = v00; oa.y = v01;
                float2 ob; ob.x = v10; ob.y = v11;
                *(float2*)&C[(size_t)r0 * Ntot + c0] = oa;
                *(float2*)&C[(size_t)r1 * Ntot + c0] = ob;
            } else {
                __nv_bfloat16* C = (__nv_bfloat16*)Cout;
                *(uint32_t*)&C[(size_t)r0 * Ntot + c0] = pack_bf16x2(v00, v01);
                *(uint32_t*)&C[(size_t)r1 * Ntot + c0] = pack_bf16x2(v10, v11);
            }
        }
    }
}

// ---------------- fused windowed attention ------------------------------------
__global__ void __launch_bounds__(256) k_attn(const float* __restrict__ rpb) {
    int blk = blockIdx.x;
    int head = blk & 7;
    int wglob = blk >> 3;
    int win = wglob & 255;
    int wh = win >> 4, ww = win & 15;
    int wt0 = wglob << 6;

    __shared__ float qs[64][36], ks[64][36], vs[64][36];
    __shared__ float at[64][65];

    int tid = threadIdx.x;
    const __nv_bfloat16* base = g_qkv + (size_t)wt0 * 768 + head * HDHEAD;
    for (int e = tid; e < 1024; e += 256) {
        int n = e >> 4, d2 = e & 15;
        const __nv_bfloat16* rowp = base + (size_t)n * 768 + d2 * 2;
        uint32_t uq = *(const uint32_t*)rowp;
        uint32_t uk = *(const uint32_t*)(rowp + 256);
        uint32_t uv = *(const uint32_t*)(rowp + 512);
        qs[n][d2 * 2] = bflo(uq); qs[n][d2 * 2 + 1] = bfhi(uq);
        ks[n][d2 * 2] = bflo(uk); ks[n][d2 * 2 + 1] = bfhi(uk);
        vs[n][d2 * 2] = bflo(uv); vs[n][d2 * 2 + 1] = bfhi(uv);
    }
    __syncthreads();

    int r = tid >> 2, cg = tid & 3;
    int ir = r >> 3, jr = r & 7;
    float qr[32];
    #pragma unroll
    for (int d4 = 0; d4 < 8; d4++) {
        float4 tq = *(const float4*)&qs[r][d4 * 4];
        qr[d4 * 4 + 0] = tq.x; qr[d4 * 4 + 1] = tq.y;
        qr[d4 * 4 + 2] = tq.z; qr[d4 * 4 + 3] = tq.w;
    }
    int regr = ((wh == 15) ? (ir < 4 ? 1 : 2) : 0) * 3 +
               ((ww == 15) ? (jr < 4 ? 1 : 2) : 0);

    float av[16];
    float mx = -1e30f;
    #pragma unroll
    for (int cc = 0; cc < 16; cc++) {
        int c = cg * 16 + cc;
        float s = 0.f;
        #pragma unroll
        for (int d4 = 0; d4 < 8; d4++) {
            float4 kk = *(const float4*)&ks[c][d4 * 4];
            s = fmaf(qr[d4 * 4 + 0], kk.x, s);
            s = fmaf(qr[d4 * 4 + 1], kk.y, s);
            s = fmaf(qr[d4 * 4 + 2], kk.z, s);
            s = fmaf(qr[d4 * 4 + 3], kk.w, s);
        }
        int ic = c >> 3, jc = c & 7;
        s += __ldg(&rpb[((ir - ic + 7) * 15 + (jr - jc + 7)) * HEADS + head]);
        int regc = ((wh == 15) ? (ic < 4 ? 1 : 2) : 0) * 3 +
                   ((ww == 15) ? (jc < 4 ? 1 : 2) : 0);
        if (regc != regr) s -= 100.f;
        av[cc] = s;
        mx = fmaxf(mx, s);
    }
    mx = fmaxf(mx, __shfl_xor_sync(0xffffffffu, mx, 1));
    mx = fmaxf(mx, __shfl_xor_sync(0xffffffffu, mx, 2));
    float sum = 0.f;
    #pragma unroll
    for (int cc = 0; cc < 16; cc++) { av[cc] = expf(av[cc] - mx); sum += av[cc]; }
    sum += __shfl_xor_sync(0xffffffffu, sum, 1);
    sum += __shfl_xor_sync(0xffffffffu, sum, 2);
    float inv = 1.f / sum;
    #pragma unroll
    for (int cc = 0; cc < 16; cc++) at[r][cg * 16 + cc] = av[cc] * inv;
    __syncthreads();

    float4 o0 = {0.f, 0.f, 0.f, 0.f}, o1 = {0.f, 0.f, 0.f, 0.f};
    #pragma unroll
    for (int m = 0; m < 64; m++) {
        float a = at[r][m];
        float4 va = *(const float4*)&vs[m][cg * 8];
        float4 vb = *(const float4*)&vs[m][cg * 8 + 4];
        o0.x = fmaf(a, va.x, o0.x); o0.y = fmaf(a, va.y, o0.y);
        o0.z = fmaf(a, va.z, o0.z); o0.w = fmaf(a, va.w, o0.w);
        o1.x = fmaf(a, vb.x, o1.x); o1.y = fmaf(a, vb.y, o1.y);
        o1.z = fmaf(a, vb.z, o1.z); o1.w = fmaf(a, vb.w, o1.w);
    }
    uint4 ou;
    ou.x = pack_bf16x2(o0.x, o0.y);
    ou.y = pack_bf16x2(o0.z, o0.w);
    ou.z = pack_bf16x2(o1.x, o1.y);
    ou.w = pack_bf16x2(o1.z, o1.w);
    *(uint4*)&g_o[(size_t)(wt0 + r) * CDIM + head * HDHEAD + cg * 8] = ou;
}

// ---------------- depthwise 3x3 conv (NHWC bf16) + bias + GELU ----------------
__global__ void __launch_bounds__(256) k_dwconv(const float* __restrict__ w9,
                                                const float* __restrict__ bconv) {
    __shared__ float wsm[HIDDIM * 9];
    int tid = threadIdx.x;
    for (int e = tid; e < HIDDIM * 9; e += 256) wsm[e] = w9[e];
    __syncthreads();

    int c0 = tid * 4;
    float wr[4][9];
    #pragma unroll
    for (int q = 0; q < 4; q++)
        #pragma unroll
        for (int k = 0; k < 9; k++) wr[q][k] = wsm[(c0 + q) * 9 + k];
    float4 bia = *(const float4*)&bconv[c0];

    int p0 = blockIdx.x * 16;
    int bb = p0 >> 14;
    int y  = (p0 >> 7) & 127;
    int x0 = p0 & 127;
    const __nv_bfloat16* base = g_h + (size_t)bb * LTOK * HIDDIM;
    __nv_bfloat16* outb = g_h2 + (size_t)bb * LTOK * HIDDIM;

    for (int px = 0; px < 16; px++) {
        int xx0 = x0 + px;
        float a0 = bia.x, a1 = bia.y, a2 = bia.z, a3 = bia.w;
        #pragma unroll
        for (int dy = -1; dy <= 1; dy++) {
            int yy = y + dy;
            if (yy < 0 || yy > 127) continue;
            #pragma unroll
            for (int dx = -1; dx <= 1; dx++) {
                int xx = xx0 + dx;
                if (xx < 0 || xx > 127) continue;
                uint2 hv = *(const uint2*)&base[((size_t)(yy * WDIM + xx)) * HIDDIM + c0];
                int ki = (dy + 1) * 3 + (dx + 1);
                a0 = fmaf(bflo(hv.x), wr[0][ki], a0);
                a1 = fmaf(bfhi(hv.x), wr[1][ki], a1);
                a2 = fmaf(bflo(hv.y), wr[2][ki], a2);
                a3 = fmaf(bfhi(hv.y), wr[3][ki], a3);
            }
        }
        a0 = 0.5f * a0 * (1.f + erff(a0 * 0.70710678118654752f));
        a1 = 0.5f * a1 * (1.f + erff(a1 * 0.70710678118654752f));
        a2 = 0.5f * a2 * (1.f + erff(a2 * 0.70710678118654752f));
        a3 = 0.5f * a3 * (1.f + erff(a3 * 0.70710678118654752f));
        uint2 ov;
        ov.x = pack_bf16x2(a0, a1);
        ov.y = pack_bf16x2(a2, a3);
        *(uint2*)&outb[((size_t)(y * WDIM + xx0)) * HIDDIM + c0] = ov;
    }
}

// ---------------- launch -------------------------------------------------------
extern "C" void kernel_launch(void* const* d_in, const int* in_sizes, int n_in,
                              void* d_out, int out_size) {
    const float* x       = (const float*)d_in[0];
    const float* norm1_w = (const float*)d_in[3];
    const float* norm1_b = (const float*)d_in[4];
    const float* wq      = (const float*)d_in[5];
    const float* bq      = (const float*)d_in[6];
    const float* wkv     = (const float*)d_in[7];
    const float* bkv     = (const float*)d_in[8];
    const float* rpb     = (const float*)d_in[9];
    const float* proj_w  = (const float*)d_in[10];
    const float* proj_b  = (const float*)d_in[11];
    const float* norm2_w = (const float*)d_in[12];
    const float* norm2_b = (const float*)d_in[13];
    const float* lin1_w  = (const float*)d_in[14];
    const float* lin1_b  = (const float*)d_in[15];
    const float* dw_w    = (const float*)d_in[16];
    const float* dw_b    = (const float*)d_in[17];
    const float* lin2_w  = (const float*)d_in[18];
    const float* lin2_b  = (const float*)d_in[19];
    float* out = (float*)d_out;

    __nv_bfloat16 *p_xwin, *p_qkv, *p_o, *p_h, *p_h2, *p_wqkv, *p_wproj, *p_wl1, *p_wl2;
    float *p_proj, *p_x1, *p_bqkv;
    cudaGetSymbolAddress((void**)&p_xwin,  g_xwin);
    cudaGetSymbolAddress((void**)&p_qkv,   g_qkv);
    cudaGetSymbolAddress((void**)&p_o,     g_o);
    cudaGetSymbolAddress((void**)&p_proj,  g_proj);
    cudaGetSymbolAddress((void**)&p_x1,    g_x1);
    cudaGetSymbolAddress((void**)&p_h,     g_h);
    cudaGetSymbolAddress((void**)&p_h2,    g_h2);
    cudaGetSymbolAddress((void**)&p_wqkv,  g_wqkv_t);
    cudaGetSymbolAddress((void**)&p_wproj, g_wproj_t);
    cudaGetSymbolAddress((void**)&p_wl1,   g_wlin1_t);
    cudaGetSymbolAddress((void**)&p_wl2,   g_wlin2_t);
    cudaGetSymbolAddress((void**)&p_bqkv,  g_bqkv);

    const float scale = 0.17677669529663687f;   // 32^-0.5

    k_prep_qkvw<<<768, 256>>>(wq, wkv, bq, bkv);
    k_transpose<<<256, 256>>>(proj_w, p_wproj, 256, 256);
    k_transpose<<<1024, 256>>>(lin1_w, p_wl1, 1024, 256);
    k_transpose<<<256, 256>>>(lin2_w, p_wl2, 256, 1024);

    // 1) LN1 + shifted-window gather
    k_ln1_gather<<<NTOK, 256>>>(x, norm1_w, norm1_b);
    // 2) qkv (bf16 out, q scaled)
    k_gemm_bf16<1><<<dim3(6, NTOK / 128), 256>>>(
        p_xwin, p_wqkv, p_bqkv, p_qkv, 256, 768, scale, nullptr);
    // 3) windowed attention
    k_attn<<<(NTOK / 64) * HEADS, 256>>>(rpb);
    // 4) proj (fp32 out)
    k_gemm_bf16<0><<<dim3(2, NTOK / 128), 256>>>(
        p_o, p_wproj, proj_b, p_proj, 256, 256, 1.f, nullptr);
    // 5) scatter + residual + LN2
    k_scatter_ln2<<<NTOK, 256>>>(x, norm2_w, norm2_b);
    // 6) lin1 + gelu (bf16 out)
    k_gemm_bf16<2><<<dim3(8, NTOK / 128), 256>>>(
        p_xwin, p_wl1, lin1_b, p_h, 256, 1024, 1.f, nullptr);
    // 7) depthwise conv + bias + gelu (bf16)
    k_dwconv<<<NTOK / 16, 256>>>(dw_w, dw_b);
    // 8) out = x1 + h2 @ lin2_w + lin2_b (fp32 out)
    k_gemm_bf16<3><<<dim3(2, NTOK / 128), 256>>>(
        p_h2, p_wl2, lin2_b, out, 1024, 256, 1.f, p_x1);
}

// round 5
// speedup vs baseline: 4.4778x; 1.7787x over previous
#include <cuda_runtime.h>
#include <cuda_bf16.h>
#include <math.h>
#include <stdint.h>

#define BATCH 4
#define HDIM 128
#define WDIM 128
#define CDIM 256
#define HIDDIM 1024
#define LTOK 16384
#define NTOK 65536
#define HEADS 8
#define HDHEAD 32

// ---------------- scratch ----------------------------------------------------
__device__ __nv_bfloat16 g_xwin[NTOK * CDIM];
__device__ __nv_bfloat16 g_qkv[NTOK * 3 * CDIM];
__device__ __nv_bfloat16 g_o[NTOK * CDIM];
__device__ float         g_proj[NTOK * CDIM];
__device__ float         g_x1[NTOK * CDIM];
__device__ __nv_bfloat16 g_h[NTOK * HIDDIM];
__device__ __nv_bfloat16 g_h2[NTOK * HIDDIM];
__device__ __nv_bfloat16 g_wqkv_t[768 * 256];
__device__ __nv_bfloat16 g_wproj_t[256 * 256];
__device__ __nv_bfloat16 g_wlin1_t[1024 * 256];
__device__ __nv_bfloat16 g_wlin2_t[256 * 1024];
__device__ float         g_bqkv[768];

// ---------------- helpers ----------------------------------------------------
__device__ __forceinline__ uint32_t smem_u32(const void* p) {
    uint32_t a;
    asm("{ .reg .u64 t; cvta.to.shared.u64 t, %1; cvt.u32.u64 %0, t; }"
        : "=r"(a) : "l"(p));
    return a;
}
__device__ __forceinline__ uint32_t pack_bf16x2(float lo, float hi) {
    uint32_t u;
    asm("cvt.rn.bf16x2.f32 %0, %1, %2;" : "=r"(u) : "f"(hi), "f"(lo));
    return u;
}
__device__ __forceinline__ float bflo(uint32_t u) { return __uint_as_float(u << 16); }
__device__ __forceinline__ float bfhi(uint32_t u) { return __uint_as_float(u & 0xffff0000u); }

#define CP_ASYNC16(saddr, gptr) \
    asm volatile("cp.async.cg.shared.global [%0], [%1], 16;" \
        :: "r"((uint32_t)(saddr)), "l"(gptr) : "memory")
#define CP_COMMIT() asm volatile("cp.async.commit_group;" ::: "memory")
#define CP_WAIT_2() asm volatile("cp.async.wait_group 2;" ::: "memory")
#define CP_WAIT_1() asm volatile("cp.async.wait_group 1;" ::: "memory")
#define CP_WAIT_0() asm volatile("cp.async.wait_group 0;" ::: "memory")

#define LDMATRIX_X4(r0, r1, r2, r3, addr) \
    asm volatile("ldmatrix.sync.aligned.m8n8.x4.shared.b16 {%0,%1,%2,%3}, [%4];" \
        : "=r"(r0), "=r"(r1), "=r"(r2), "=r"(r3) : "r"(addr))
#define LDMATRIX_X4_T(r0, r1, r2, r3, addr) \
    asm volatile("ldmatrix.sync.aligned.m8n8.x4.trans.shared.b16 {%0,%1,%2,%3}, [%4];" \
        : "=r"(r0), "=r"(r1), "=r"(r2), "=r"(r3) : "r"(addr))

#define MMA_BF16(c, a0, a1, a2, a3, b0, b1) \
    asm volatile("mma.sync.aligned.m16n8k16.row.col.f32.bf16.bf16.f32 " \
        "{%0,%1,%2,%3},{%4,%5,%6,%7},{%8,%9},{%0,%1,%2,%3};" \
        : "+f"((c)[0]), "+f"((c)[1]), "+f"((c)[2]), "+f"((c)[3]) \
        : "r"(a0), "r"(a1), "r"(a2), "r"(a3), "r"(b0), "r"(b1))

// ---------------- weight prep -------------------------------------------------
__global__ void k_prep_qkvw(const float* __restrict__ wq, const float* __restrict__ wkv,
                            const float* __restrict__ bq, const float* __restrict__ bkv) {
    int n = blockIdx.x, k = threadIdx.x;
    float v = (n < 256) ? wq[k * 256 + n] : wkv[k * 512 + (n - 256)];
    g_wqkv_t[n * 256 + k] = __float2bfloat16_rn(v);
    if (k == 0) g_bqkv[n] = (n < 256) ? bq[n] : bkv[n - 256];
}
__global__ void k_transpose(const float* __restrict__ in, __nv_bfloat16* __restrict__ out,
                            int N, int K) {
    int n = blockIdx.x;
    for (int k = threadIdx.x; k < K; k += blockDim.x)
        out[(size_t)n * K + k] = __float2bfloat16_rn(in[(size_t)k * N + n]);
}

// ---------------- LN1 + shifted-window gather (warp per token) ----------------
__global__ void __launch_bounds__(256) k_ln1_gather(const float* __restrict__ x,
                                                    const float* __restrict__ w,
                                                    const float* __restrict__ b) {
    int wt = blockIdx.x * 8 + (threadIdx.x >> 5);
    int lane = threadIdx.x & 31;
    int bb = wt >> 14, rem = wt & 16383;
    int win = rem >> 6, n = rem & 63;
    int wh = win >> 4, ww = win & 15;
    int i = n >> 3, j = n & 7;
    int h = (wh * 8 + i + 4) & 127, wc = (ww * 8 + j + 4) & 127;
    const float4* src = (const float4*)(x + ((size_t)(bb * LTOK + h * WDIM + wc)) * CDIM);
    float4 v0 = src[lane], v1 = src[lane + 32];
    float s = v0.x + v0.y + v0.z + v0.w + v1.x + v1.y + v1.z + v1.w;
    float s2 = v0.x*v0.x + v0.y*v0.y + v0.z*v0.z + v0.w*v0.w
             + v1.x*v1.x + v1.y*v1.y + v1.z*v1.z + v1.w*v1.w;
    #pragma unroll
    for (int o = 16; o > 0; o >>= 1) {
        s  += __shfl_xor_sync(0xffffffffu, s, o);
        s2 += __shfl_xor_sync(0xffffffffu, s2, o);
    }
    float m = s * (1.f / 256.f);
    float rstd = rsqrtf(s2 * (1.f / 256.f) - m * m + 1e-5f);
    int c = lane * 4;
    const float4* w4 = (const float4*)w;
    const float4* b4 = (const float4*)b;
    float4 wa = w4[lane], ba = b4[lane], wb = w4[lane + 32], bc = b4[lane + 32];
    uint2 oA, oB;
    oA.x = pack_bf16x2((v0.x - m) * rstd * wa.x + ba.x, (v0.y - m) * rstd * wa.y + ba.y);
    oA.y = pack_bf16x2((v0.z - m) * rstd * wa.z + ba.z, (v0.w - m) * rstd * wa.w + ba.w);
    oB.x = pack_bf16x2((v1.x - m) * rstd * wb.x + bc.x, (v1.y - m) * rstd * wb.y + bc.y);
    oB.y = pack_bf16x2((v1.z - m) * rstd * wb.z + bc.z, (v1.w - m) * rstd * wb.w + bc.w);
    *(uint2*)&g_xwin[(size_t)wt * CDIM + c] = oA;
    *(uint2*)&g_xwin[(size_t)wt * CDIM + c + 128] = oB;
}

// ---------------- scatter + residual + LN2 (warp per token) -------------------
__global__ void __launch_bounds__(256) k_scatter_ln2(const float* __restrict__ x,
                                                     const float* __restrict__ w,
                                                     const float* __restrict__ b) {
    int wt = blockIdx.x * 8 + (threadIdx.x >> 5);
    int lane = threadIdx.x & 31;
    int bb = wt >> 14, rem = wt & 16383;
    int win = rem >> 6, n = rem & 63;
    int wh = win >> 4, ww = win & 15;
    int i = n >> 3, j = n & 7;
    int h = (wh * 8 + i + 4) & 127, wc = (ww * 8 + j + 4) & 127;
    size_t dst = ((size_t)(bb * LTOK + h * WDIM + wc)) * CDIM;
    const float4* xs = (const float4*)(x + dst);
    const float4* ps = (const float4*)(g_proj + (size_t)wt * CDIM);
    float4 v0 = xs[lane], v1 = xs[lane + 32];
    float4 p0 = ps[lane], p1 = ps[lane + 32];
    v0.x += p0.x; v0.y += p0.y; v0.z += p0.z; v0.w += p0.w;
    v1.x += p1.x; v1.y += p1.y; v1.z += p1.z; v1.w += p1.w;
    float4* x1s = (float4*)(g_x1 + dst);
    x1s[lane] = v0; x1s[lane + 32] = v1;
    float s = v0.x + v0.y + v0.z + v0.w + v1.x + v1.y + v1.z + v1.w;
    float s2 = v0.x*v0.x + v0.y*v0.y + v0.z*v0.z + v0.w*v0.w
             + v1.x*v1.x + v1.y*v1.y + v1.z*v1.z + v1.w*v1.w;
    #pragma unroll
    for (int o = 16; o > 0; o >>= 1) {
        s  += __shfl_xor_sync(0xffffffffu, s, o);
        s2 += __shfl_xor_sync(0xffffffffu, s2, o);
    }
    float m = s * (1.f / 256.f);
    float rstd = rsqrtf(s2 * (1.f / 256.f) - m * m + 1e-5f);
    int c = lane * 4;
    const float4* w4 = (const float4*)w;
    const float4* b4 = (const float4*)b;
    float4 wa = w4[lane], ba = b4[lane], wb = w4[lane + 32], bc = b4[lane + 32];
    uint2 oA, oB;
    oA.x = pack_bf16x2((v0.x - m) * rstd * wa.x + ba.x, (v0.y - m) * rstd * wa.y + ba.y);
    oA.y = pack_bf16x2((v0.z - m) * rstd * wa.z + ba.z, (v0.w - m) * rstd * wa.w + ba.w);
    oB.x = pack_bf16x2((v1.x - m) * rstd * wb.x + bc.x, (v1.y - m) * rstd * wb.y + bc.y);
    oB.y = pack_bf16x2((v1.z - m) * rstd * wb.z + bc.z, (v1.w - m) * rstd * wb.w + bc.w);
    *(uint2*)&g_xwin[dst + c] = oA;
    *(uint2*)&g_xwin[dst + c + 128] = oB;
}

// ============ bf16 mma GEMM (unchanged from R4) ===============================
#define STAGE_B 8192

__device__ __forceinline__ void load_stage_bf(uint32_t sb, int s,
                                              const __nv_bfloat16* __restrict__ Ab,
                                              const __nv_bfloat16* __restrict__ Bb,
                                              int K, int kc, int tid) {
    const __nv_bfloat16* Ag = Ab + kc * 32;
    const __nv_bfloat16* Bg = Bb + kc * 32;
    uint32_t abase = sb + s * STAGE_B;
    uint32_t bbase = sb + 3 * STAGE_B + s * STAGE_B;
    #pragma unroll
    for (int i = 0; i < 2; i++) {
        int idx = tid + (i << 8);
        int row = idx >> 2, ch = idx & 3;
        int sw = ch ^ ((row >> 1) & 3);
        CP_ASYNC16(abase + row * 64 + sw * 16, Ag + (size_t)row * K + ch * 8);
        CP_ASYNC16(bbase + row * 64 + sw * 16, Bg + (size_t)row * K + ch * 8);
    }
    CP_COMMIT();
}

template <int EPI>
__global__ void __launch_bounds__(256) k_gemm_bf16(
    const __nv_bfloat16* __restrict__ A, const __nv_bfloat16* __restrict__ Bt,
    const float* __restrict__ bias, void* __restrict__ Cout,
    int K, int Ntot, float scale, const float* __restrict__ res)
{
    __shared__ __align__(16) char smem[6 * STAGE_B];
    uint32_t sb = smem_u32(smem);

    int tid = threadIdx.x, lane = tid & 31, wid = tid >> 5;
    int wm = wid >> 2, wn = wid & 3;
    int bm = blockIdx.y << 7, bn = blockIdx.x << 7;
    const __nv_bfloat16* Ab = A + (size_t)bm * K;
    const __nv_bfloat16* Bb = Bt + (size_t)bn * K;
    int nKC = K >> 5;

    int rA = (lane & 7) + ((lane >> 3) & 1) * 8;
    int cA = lane >> 4;
    int selA = (rA >> 1) & 3;
    uint32_t aRowOff = (uint32_t)(wm * 64 + rA) * 64;
    uint32_t aChunkOff[2] = { (uint32_t)((0 + cA) ^ selA) * 16,
                              (uint32_t)((2 + cA) ^ selA) * 16 };
    int rB = lane & 7, cB = lane >> 3;
    int selB = (rB >> 1) & 3;
    uint32_t bOff = (uint32_t)(wn * 32 + rB) * 64 + (uint32_t)(cB ^ selB) * 16;

    float acc[4][4][4];
    #pragma unroll
    for (int mt = 0; mt < 4; mt++)
        #pragma unroll
        for (int nt = 0; nt < 4; nt++)
            #pragma unroll
            for (int q = 0; q < 4; q++) acc[mt][nt][q] = 0.f;

    load_stage_bf(sb, 0, Ab, Bb, K, 0, tid);
    if (nKC > 1) load_stage_bf(sb, 1, Ab, Bb, K, 1, tid);
    else CP_COMMIT();

    for (int kc = 0; kc < nKC; kc++) {
        if (kc + 2 < nKC) { load_stage_bf(sb, (kc + 2) % 3, Ab, Bb, K, kc + 2, tid); CP_WAIT_2(); }
        else if (kc + 1 < nKC) { CP_WAIT_1(); }
        else { CP_WAIT_0(); }
        __syncthreads();

        uint32_t asp = sb + (kc % 3) * STAGE_B;
        uint32_t bsp = sb + 3 * STAGE_B + (kc % 3) * STAGE_B;

        uint32_t bfr[4][4];
        #pragma unroll
        for (int nt = 0; nt < 4; nt++)
            LDMATRIX_X4(bfr[nt][0], bfr[nt][1], bfr[nt][2], bfr[nt][3],
                        bsp + bOff + nt * 512);
        #pragma unroll
        for (int kk = 0; kk < 2; kk++) {
            #pragma unroll
            for (int mt = 0; mt < 4; mt++) {
                uint32_t a0, a1, a2, a3;
                LDMATRIX_X4(a0, a1, a2, a3, asp + aRowOff + mt * 1024 + aChunkOff[kk]);
                #pragma unroll
                for (int nt = 0; nt < 4; nt++)
                    MMA_BF16(acc[mt][nt], a0, a1, a2, a3,
                             bfr[nt][kk * 2], bfr[nt][kk * 2 + 1]);
            }
        }
        __syncthreads();
    }

    int g = lane >> 2, t = lane & 3;
    #pragma unroll
    for (int mt = 0; mt < 4; mt++) {
        int r0 = bm + wm * 64 + mt * 16 + g;
        int r1 = r0 + 8;
        #pragma unroll
        for (int nt = 0; nt < 4; nt++) {
            int c0 = bn + wn * 32 + nt * 8 + t * 2;
            float2 b2 = *(const float2*)&bias[c0];
            float v00 = acc[mt][nt][0] + b2.x;
            float v01 = acc[mt][nt][1] + b2.y;
            float v10 = acc[mt][nt][2] + b2.x;
            float v11 = acc[mt][nt][3] + b2.y;
            if (EPI == 1) {
                if (c0 < 256) { v00 *= scale; v01 *= scale; v10 *= scale; v11 *= scale; }
            }
            if (EPI == 2) {
                v00 = 0.5f * v00 * (1.f + erff(v00 * 0.70710678118654752f));
                v01 = 0.5f * v01 * (1.f + erff(v01 * 0.70710678118654752f));
                v10 = 0.5f * v10 * (1.f + erff(v10 * 0.70710678118654752f));
                v11 = 0.5f * v11 * (1.f + erff(v11 * 0.70710678118654752f));
            }
            if (EPI == 3) {
                float2 ra = *(const float2*)&res[(size_t)r0 * Ntot + c0];
                float2 rb = *(const float2*)&res[(size_t)r1 * Ntot + c0];
                v00 += ra.x; v01 += ra.y; v10 += rb.x; v11 += rb.y;
            }
            if (EPI == 0 || EPI == 3) {
                float* C = (float*)Cout;
                float2 oa; oa.x = v00; oa.y = v01;
                float2 ob; ob.x = v10; ob.y = v11;
                *(float2*)&C[(size_t)r0 * Ntot + c0] = oa;
                *(float2*)&C[(size_t)r1 * Ntot + c0] = ob;
            } else {
                __nv_bfloat16* C = (__nv_bfloat16*)Cout;
                *(uint32_t*)&C[(size_t)r0 * Ntot + c0] = pack_bf16x2(v00, v01);
                *(uint32_t*)&C[(size_t)r1 * Ntot + c0] = pack_bf16x2(v10, v11);
            }
        }
    }
}

// ================= mma-based windowed attention ===============================
// block = one window (512 thr, 16 warps). warp w: head = w>>1, M-half = w&1.
// smem: Q,K,V 64x256 bf16 each (rows 512B, 16B-chunk swizzle c^(r&7)) + rpb.
#define ATT_SMEM (3 * 32768 + 1800 * 4)

__global__ void __launch_bounds__(512) k_attn2(const float* __restrict__ rpb) {
    extern __shared__ __align__(16) char sm[];
    uint32_t sb = smem_u32(sm);
    float* srpb = (float*)(sm + 98304);

    int wglob = blockIdx.x;
    int win = wglob & 255;
    int wh = win >> 4, ww = win & 15;
    int wt0 = wglob << 6;
    int tid = threadIdx.x;

    for (int iv = tid; iv < 6144; iv += 512) {
        int mat = iv >> 11;
        int rem = iv & 2047;
        int row = rem >> 5, ch = rem & 31;
        uint4 v = *(const uint4*)&g_qkv[(size_t)(wt0 + row) * 768 + mat * 256 + ch * 8];
        *(uint4*)(sm + mat * 32768 + row * 512 + ((ch ^ (row & 7)) << 4)) = v;
    }
    for (int iv = tid; iv < 1800; iv += 512) srpb[iv] = rpb[iv];
    __syncthreads();

    int lane = tid & 31, wid = tid >> 5;
    int h = wid >> 1, mh = wid & 1;
    int m0 = mh * 32;
    int g = lane >> 2, t = lane & 3;
    uint32_t sQ = sb, sK = sb + 32768, sV = sb + 65536;

    // ---- S = Q K^T ----
    float S[2][8][4];
    #pragma unroll
    for (int mt = 0; mt < 2; mt++)
        #pragma unroll
        for (int nt = 0; nt < 8; nt++)
            #pragma unroll
            for (int q = 0; q < 4; q++) S[mt][nt][q] = 0.f;

    #pragma unroll
    for (int s = 0; s < 2; s++) {
        uint32_t a[2][4];
        #pragma unroll
        for (int mt = 0; mt < 2; mt++) {
            int row = m0 + mt * 16 + (lane & 15);
            int ch = h * 4 + s * 2 + (lane >> 4);
            LDMATRIX_X4(a[mt][0], a[mt][1], a[mt][2], a[mt][3],
                        sQ + row * 512 + (((ch) ^ (row & 7)) << 4));
        }
        uint32_t bb[8][2];
        #pragma unroll
        for (int p = 0; p < 4; p++) {
            int row = p * 16 + (lane & 7) + ((lane >> 4) & 1) * 8;
            int ch = h * 4 + s * 2 + ((lane >> 3) & 1);
            LDMATRIX_X4(bb[2 * p][0], bb[2 * p][1], bb[2 * p + 1][0], bb[2 * p + 1][1],
                        sK + row * 512 + ((ch ^ (row & 7)) << 4));
        }
        #pragma unroll
        for (int mt = 0; mt < 2; mt++)
            #pragma unroll
            for (int nt = 0; nt < 8; nt++)
                MMA_BF16(S[mt][nt], a[mt][0], a[mt][1], a[mt][2], a[mt][3],
                         bb[nt][0], bb[nt][1]);
    }

    // ---- bias + mask + softmax + pack to bf16 A-fragments ----
    int mwh = (wh == 15), mww = (ww == 15);
    int jc0 = t * 2, jc1 = t * 2 + 1;
    int cregj0 = mww ? (jc0 < 4 ? 1 : 2) : 0;
    int cregj1 = mww ? (jc1 < 4 ? 1 : 2) : 0;

    uint32_t pa[2][4][4];
    #pragma unroll
    for (int mt = 0; mt < 2; mt++) {
        int r0 = m0 + mt * 16 + g;
        int r1 = r0 + 8;
        int ir0 = r0 >> 3, jr0 = r0 & 7;
        int ir1 = r1 >> 3;   // jr same
        int rregi0 = mwh ? (ir0 < 4 ? 1 : 2) : 0;
        int rregi1 = mwh ? (ir1 < 4 ? 1 : 2) : 0;
        int rregj = mww ? (jr0 < 4 ? 1 : 2) : 0;
        int reg0 = rregi0 * 3 + rregj;
        int reg1 = rregi1 * 3 + rregj;
        float mx0 = -1e30f, mx1 = -1e30f;
        #pragma unroll
        for (int nt = 0; nt < 8; nt++) {
            int cregi = mwh ? (nt < 4 ? 1 : 2) : 0;
            int base0 = (ir0 - nt + 7) * 15 + jr0 + 7;
            int base1 = (ir1 - nt + 7) * 15 + jr0 + 7;
            float b00 = srpb[(base0 - jc0) * 8 + h];
            float b01 = srpb[(base0 - jc1) * 8 + h];
            float b10 = srpb[(base1 - jc0) * 8 + h];
            float b11 = srpb[(base1 - jc1) * 8 + h];
            int c0r = cregi * 3 + cregj0, c1r = cregi * 3 + cregj1;
            S[mt][nt][0] += b00 + ((c0r != reg0) ? -100.f : 0.f);
            S[mt][nt][1] += b01 + ((c1r != reg0) ? -100.f : 0.f);
            S[mt][nt][2] += b10 + ((c0r != reg1) ? -100.f : 0.f);
            S[mt][nt][3] += b11 + ((c1r != reg1) ? -100.f : 0.f);
            mx0 = fmaxf(mx0, fmaxf(S[mt][nt][0], S[mt][nt][1]));
            mx1 = fmaxf(mx1, fmaxf(S[mt][nt][2], S[mt][nt][3]));
        }
        mx0 = fmaxf(mx0, __shfl_xor_sync(0xffffffffu, mx0, 1));
        mx0 = fmaxf(mx0, __shfl_xor_sync(0xffffffffu, mx0, 2));
        mx1 = fmaxf(mx1, __shfl_xor_sync(0xffffffffu, mx1, 1));
        mx1 = fmaxf(mx1, __shfl_xor_sync(0xffffffffu, mx1, 2));
        float sum0 = 0.f, sum1 = 0.f;
        #pragma unroll
        for (int nt = 0; nt < 8; nt++) {
            S[mt][nt][0] = expf(S[mt][nt][0] - mx0);
            S[mt][nt][1] = expf(S[mt][nt][1] - mx0);
            S[mt][nt][2] = expf(S[mt][nt][2] - mx1);
            S[mt][nt][3] = expf(S[mt][nt][3] - mx1);
            sum0 += S[mt][nt][0] + S[mt][nt][1];
            sum1 += S[mt][nt][2] + S[mt][nt][3];
        }
        sum0 += __shfl_xor_sync(0xffffffffu, sum0, 1);
        sum0 += __shfl_xor_sync(0xffffffffu, sum0, 2);
        sum1 += __shfl_xor_sync(0xffffffffu, sum1, 1);
        sum1 += __shfl_xor_sync(0xffffffffu, sum1, 2);
        float inv0 = 1.f / sum0, inv1 = 1.f / sum1;
        #pragma unroll
        for (int s = 0; s < 4; s++) {
            pa[mt][s][0] = pack_bf16x2(S[mt][2*s][0] * inv0, S[mt][2*s][1] * inv0);
            pa[mt][s][1] = pack_bf16x2(S[mt][2*s][2] * inv1, S[mt][2*s][3] * inv1);
            pa[mt][s][2] = pack_bf16x2(S[mt][2*s+1][0] * inv0, S[mt][2*s+1][1] * inv0);
            pa[mt][s][3] = pack_bf16x2(S[mt][2*s+1][2] * inv1, S[mt][2*s+1][3] * inv1);
        }
    }

    // ---- O = P V ----
    float O[2][4][4];
    #pragma unroll
    for (int mt = 0; mt < 2; mt++)
        #pragma unroll
        for (int dt = 0; dt < 4; dt++)
            #pragma unroll
            for (int q = 0; q < 4; q++) O[mt][dt][q] = 0.f;

    #pragma unroll
    for (int s = 0; s < 4; s++) {
        uint32_t pb[4][2];
        #pragma unroll
        for (int half = 0; half < 2; half++) {
            int row = s * 16 + (lane & 7) + ((lane >> 3) & 1) * 8;
            int ch = h * 4 + half * 2 + (lane >> 4);
            LDMATRIX_X4_T(pb[half*2][0], pb[half*2][1], pb[half*2+1][0], pb[half*2+1][1],
                          sV + row * 512 + ((ch ^ (row & 7)) << 4));
        }
        #pragma unroll
        for (int mt = 0; mt < 2; mt++)
            #pragma unroll
            for (int dt = 0; dt < 4; dt++)
                MMA_BF16(O[mt][dt], pa[mt][s][0], pa[mt][s][1], pa[mt][s][2], pa[mt][s][3],
                         pb[dt][0], pb[dt][1]);
    }

    #pragma unroll
    for (int mt = 0; mt < 2; mt++) {
        int r0 = wt0 + m0 + mt * 16 + g;
        #pragma unroll
        for (int dt = 0; dt < 4; dt++) {
            int col = h * 32 + dt * 8 + t * 2;
            *(uint32_t*)&g_o[(size_t)r0 * 256 + col]       = pack_bf16x2(O[mt][dt][0], O[mt][dt][1]);
            *(uint32_t*)&g_o[(size_t)(r0 + 8) * 256 + col] = pack_bf16x2(O[mt][dt][2], O[mt][dt][3]);
        }
    }
}

// ---------------- depthwise 3x3 conv + bias + GELU (column rotation) ----------
__device__ __forceinline__ float4 ldh4(const __nv_bfloat16* base, int yy, int xx, int c0) {
    if ((unsigned)yy > 127u || (unsigned)xx > 127u) return make_float4(0.f, 0.f, 0.f, 0.f);
    uint2 hv = *(const uint2*)&base[((size_t)(yy * WDIM + xx)) * HIDDIM + c0];
    return make_float4(bflo(hv.x), bfhi(hv.x), bflo(hv.y), bfhi(hv.y));
}

__global__ void __launch_bounds__(256) k_dwconv(const float* __restrict__ w9,
                                                const float* __restrict__ bconv) {
    __shared__ float wsm[HIDDIM * 9];
    int tid = threadIdx.x;
    for (int e = tid; e < HIDDIM * 9; e += 256) wsm[e] = w9[e];
    __syncthreads();

    int c0 = tid * 4;
    float wr[4][9];
    #pragma unroll
    for (int q = 0; q < 4; q++)
        #pragma unroll
        for (int k = 0; k < 9; k++) wr[q][k] = wsm[(c0 + q) * 9 + k];
    float4 bia = *(const float4*)&bconv[c0];

    int p0 = blockIdx.x * 16;
    int bb = p0 >> 14;
    int y  = (p0 >> 7) & 127;
    int x0 = p0 & 127;
    const __nv_bfloat16* base = g_h + (size_t)bb * LTOK * HIDDIM;
    __nv_bfloat16* outb = g_h2 + (size_t)bb * LTOK * HIDDIM;

    float4 L[3], Cc[3], R[3];
    #pragma unroll
    for (int dy = 0; dy < 3; dy++) {
        L[dy]  = ldh4(base, y + dy - 1, x0 - 1, c0);
        Cc[dy] = ldh4(base, y + dy - 1, x0, c0);
    }

    for (int px = 0; px < 16; px++) {
        int xx = x0 + px;
        #pragma unroll
        for (int dy = 0; dy < 3; dy++) R[dy] = ldh4(base, y + dy - 1, xx + 1, c0);
        float a0 = bia.x, a1 = bia.y, a2 = bia.z, a3 = bia.w;
        #pragma unroll
        for (int dy = 0; dy < 3; dy++) {
            a0 = fmaf(L[dy].x,  wr[0][dy*3+0], a0);
            a0 = fmaf(Cc[dy].x, wr[0][dy*3+1], a0);
            a0 = fmaf(R[dy].x,  wr[0][dy*3+2], a0);
            a1 = fmaf(L[dy].y,  wr[1][dy*3+0], a1);
            a1 = fmaf(Cc[dy].y, wr[1][dy*3+1], a1);
            a1 = fmaf(R[dy].y,  wr[1][dy*3+2], a1);
            a2 = fmaf(L[dy].z,  wr[2][dy*3+0], a2);
            a2 = fmaf(Cc[dy].z, wr[2][dy*3+1], a2);
            a2 = fmaf(R[dy].z,  wr[2][dy*3+2], a2);
            a3 = fmaf(L[dy].w,  wr[3][dy*3+0], a3);
            a3 = fmaf(Cc[dy].w, wr[3][dy*3+1], a3);
            a3 = fmaf(R[dy].w,  wr[3][dy*3+2], a3);
        }
        a0 = 0.5f * a0 * (1.f + erff(a0 * 0.70710678118654752f));
        a1 = 0.5f * a1 * (1.f + erff(a1 * 0.70710678118654752f));
        a2 = 0.5f * a2 * (1.f + erff(a2 * 0.70710678118654752f));
        a3 = 0.5f * a3 * (1.f + erff(a3 * 0.70710678118654752f));
        uint2 ov;
        ov.x = pack_bf16x2(a0, a1);
        ov.y = pack_bf16x2(a2, a3);
        *(uint2*)&outb[((size_t)(y * WDIM + xx)) * HIDDIM + c0] = ov;
        #pragma unroll
        for (int dy = 0; dy < 3; dy++) { L[dy] = Cc[dy]; Cc[dy] = R[dy]; }
    }
}

// ---------------- launch -------------------------------------------------------
extern "C" void kernel_launch(void* const* d_in, const int* in_sizes, int n_in,
                              void* d_out, int out_size) {
    const float* x       = (const float*)d_in[0];
    const float* norm1_w = (const float*)d_in[3];
    const float* norm1_b = (const float*)d_in[4];
    const float* wq      = (const float*)d_in[5];
    const float* bq      = (const float*)d_in[6];
    const float* wkv     = (const float*)d_in[7];
    const float* bkv     = (const float*)d_in[8];
    const float* rpb     = (const float*)d_in[9];
    const float* proj_w  = (const float*)d_in[10];
    const float* proj_b  = (const float*)d_in[11];
    const float* norm2_w = (const float*)d_in[12];
    const float* norm2_b = (const float*)d_in[13];
    const float* lin1_w  = (const float*)d_in[14];
    const float* lin1_b  = (const float*)d_in[15];
    const float* dw_w    = (const float*)d_in[16];
    const float* dw_b    = (const float*)d_in[17];
    const float* lin2_w  = (const float*)d_in[18];
    const float* lin2_b  = (const float*)d_in[19];
    float* out = (float*)d_out;

    __nv_bfloat16 *p_xwin, *p_qkv, *p_o, *p_h, *p_h2, *p_wqkv, *p_wproj, *p_wl1, *p_wl2;
    float *p_proj, *p_x1, *p_bqkv;
    cudaGetSymbolAddress((void**)&p_xwin,  g_xwin);
    cudaGetSymbolAddress((void**)&p_qkv,   g_qkv);
    cudaGetSymbolAddress((void**)&p_o,     g_o);
    cudaGetSymbolAddress((void**)&p_proj,  g_proj);
    cudaGetSymbolAddress((void**)&p_x1,    g_x1);
    cudaGetSymbolAddress((void**)&p_h,     g_h);
    cudaGetSymbolAddress((void**)&p_h2,    g_h2);
    cudaGetSymbolAddress((void**)&p_wqkv,  g_wqkv_t);
    cudaGetSymbolAddress((void**)&p_wproj, g_wproj_t);
    cudaGetSymbolAddress((void**)&p_wl1,   g_wlin1_t);
    cudaGetSymbolAddress((void**)&p_wl2,   g_wlin2_t);
    cudaGetSymbolAddress((void**)&p_bqkv,  g_bqkv);

    cudaFuncSetAttribute(k_attn2, cudaFuncAttributeMaxDynamicSharedMemorySize, ATT_SMEM);

    const float scale = 0.17677669529663687f;

    k_prep_qkvw<<<768, 256>>>(wq, wkv, bq, bkv);
    k_transpose<<<256, 256>>>(proj_w, p_wproj, 256, 256);
    k_transpose<<<1024, 256>>>(lin1_w, p_wl1, 1024, 256);
    k_transpose<<<256, 256>>>(lin2_w, p_wl2, 256, 1024);

    k_ln1_gather<<<NTOK / 8, 256>>>(x, norm1_w, norm1_b);
    k_gemm_bf16<1><<<dim3(6, NTOK / 128), 256>>>(
        p_xwin, p_wqkv, p_bqkv, p_qkv, 256, 768, scale, nullptr);
    k_attn2<<<NTOK / 64, 512, ATT_SMEM>>>(rpb);
    k_gemm_bf16<0><<<dim3(2, NTOK / 128), 256>>>(
        p_o, p_wproj, proj_b, p_proj, 256, 256, 1.f, nullptr);
    k_scatter_ln2<<<NTOK / 8, 256>>>(x, norm2_w, norm2_b);
    k_gemm_bf16<2><<<dim3(8, NTOK / 128), 256>>>(
        p_xwin, p_wl1, lin1_b, p_h, 256, 1024, 1.f, nullptr);
    k_dwconv<<<NTOK / 16, 256>>>(dw_w, dw_b);
    k_gemm_bf16<3><<<dim3(2, NTOK / 128), 256>>>(
        p_h2, p_wl2, lin2_b, out, 1024, 256, 1.f, p_x1);
}

// round 6
// speedup vs baseline: 4.5612x; 1.0186x over previous
#include <cuda_runtime.h>
#include <cuda_bf16.h>
#include <math.h>
#include <stdint.h>

#define BATCH 4
#define HDIM 128
#define WDIM 128
#define CDIM 256
#define HIDDIM 1024
#define LTOK 16384
#define NTOK 65536
#define HEADS 8
#define HDHEAD 32

// ---------------- scratch ----------------------------------------------------
__device__ __nv_bfloat16 g_xwin[NTOK * CDIM];
__device__ __nv_bfloat16 g_qkv[NTOK * 3 * CDIM];
__device__ __nv_bfloat16 g_o[NTOK * CDIM];
__device__ float         g_x1[NTOK * CDIM];
__device__ __nv_bfloat16 g_h[NTOK * HIDDIM];
__device__ __nv_bfloat16 g_h2[NTOK * HIDDIM];
__device__ __nv_bfloat16 g_wqkv_t[768 * 256];
__device__ __nv_bfloat16 g_wproj_t[256 * 256];
__device__ __nv_bfloat16 g_wlin1_t[1024 * 256];
__device__ __nv_bfloat16 g_wlin2_t[256 * 1024];
__device__ float         g_bqkv[768];

// ---------------- helpers ----------------------------------------------------
__device__ __forceinline__ uint32_t smem_u32(const void* p) {
    uint32_t a;
    asm("{ .reg .u64 t; cvta.to.shared.u64 t, %1; cvt.u32.u64 %0, t; }"
        : "=r"(a) : "l"(p));
    return a;
}
__device__ __forceinline__ uint32_t pack_bf16x2(float lo, float hi) {
    uint32_t u;
    asm("cvt.rn.bf16x2.f32 %0, %1, %2;" : "=r"(u) : "f"(hi), "f"(lo));
    return u;
}
__device__ __forceinline__ float bflo(uint32_t u) { return __uint_as_float(u << 16); }
__device__ __forceinline__ float bfhi(uint32_t u) { return __uint_as_float(u & 0xffff0000u); }

// window-token index -> token index (reverse shifted-window permutation)
__device__ __forceinline__ int wt2dst(int wt) {
    int bb = wt >> 14, rem = wt & 16383;
    int win = rem >> 6, n = rem & 63;
    int wh = win >> 4, ww = win & 15;
    int i = n >> 3, j = n & 7;
    int h = (wh * 8 + i + 4) & 127, wc = (ww * 8 + j + 4) & 127;
    return bb * LTOK + h * WDIM + wc;
}

#define CP_ASYNC16(saddr, gptr) \
    asm volatile("cp.async.cg.shared.global [%0], [%1], 16;" \
        :: "r"((uint32_t)(saddr)), "l"(gptr) : "memory")
#define CP_COMMIT() asm volatile("cp.async.commit_group;" ::: "memory")
#define CP_WAIT_2() asm volatile("cp.async.wait_group 2;" ::: "memory")
#define CP_WAIT_1() asm volatile("cp.async.wait_group 1;" ::: "memory")
#define CP_WAIT_0() asm volatile("cp.async.wait_group 0;" ::: "memory")

#define LDMATRIX_X4(r0, r1, r2, r3, addr) \
    asm volatile("ldmatrix.sync.aligned.m8n8.x4.shared.b16 {%0,%1,%2,%3}, [%4];" \
        : "=r"(r0), "=r"(r1), "=r"(r2), "=r"(r3) : "r"(addr))
#define LDMATRIX_X4_T(r0, r1, r2, r3, addr) \
    asm volatile("ldmatrix.sync.aligned.m8n8.x4.trans.shared.b16 {%0,%1,%2,%3}, [%4];" \
        : "=r"(r0), "=r"(r1), "=r"(r2), "=r"(r3) : "r"(addr))

#define MMA_BF16(c, a0, a1, a2, a3, b0, b1) \
    asm volatile("mma.sync.aligned.m16n8k16.row.col.f32.bf16.bf16.f32 " \
        "{%0,%1,%2,%3},{%4,%5,%6,%7},{%8,%9},{%0,%1,%2,%3};" \
        : "+f"((c)[0]), "+f"((c)[1]), "+f"((c)[2]), "+f"((c)[3]) \
        : "r"(a0), "r"(a1), "r"(a2), "r"(a3), "r"(b0), "r"(b1))

// ---------------- merged weight prep ------------------------------------------
__global__ void __launch_bounds__(256) k_prep_all(
    const float* __restrict__ wq, const float* __restrict__ wkv,
    const float* __restrict__ bq, const float* __restrict__ bkv,
    const float* __restrict__ proj_w, const float* __restrict__ lin1_w,
    const float* __restrict__ lin2_w)
{
    int blk = blockIdx.x;
    int k = threadIdx.x;
    if (blk < 768) {
        float v = (blk < 256) ? wq[k * 256 + blk] : wkv[k * 512 + (blk - 256)];
        g_wqkv_t[blk * 256 + k] = __float2bfloat16_rn(v);
        if (k == 0) g_bqkv[blk] = (blk < 256) ? bq[blk] : bkv[blk - 256];
    } else if (blk < 1024) {
        int n = blk - 768;
        g_wproj_t[n * 256 + k] = __float2bfloat16_rn(proj_w[k * 256 + n]);
    } else if (blk < 2048) {
        int n = blk - 1024;
        g_wlin1_t[n * 256 + k] = __float2bfloat16_rn(lin1_w[k * 1024 + n]);
    } else {
        int n = blk - 2048;
        #pragma unroll
        for (int j = 0; j < 4; j++) {
            int kk = k + j * 256;
            g_wlin2_t[n * 1024 + kk] = __float2bfloat16_rn(lin2_w[(size_t)kk * 256 + n]);
        }
    }
}

// ---------------- LN1 + shifted-window gather (warp per token) ----------------
__global__ void __launch_bounds__(256) k_ln1_gather(const float* __restrict__ x,
                                                    const float* __restrict__ w,
                                                    const float* __restrict__ b) {
    int wt = blockIdx.x * 8 + (threadIdx.x >> 5);
    int lane = threadIdx.x & 31;
    int dst = wt2dst(wt);
    const float4* src = (const float4*)(x + (size_t)dst * CDIM);
    float4 v0 = src[lane], v1 = src[lane + 32];
    float s = v0.x + v0.y + v0.z + v0.w + v1.x + v1.y + v1.z + v1.w;
    float s2 = v0.x*v0.x + v0.y*v0.y + v0.z*v0.z + v0.w*v0.w
             + v1.x*v1.x + v1.y*v1.y + v1.z*v1.z + v1.w*v1.w;
    #pragma unroll
    for (int o = 16; o > 0; o >>= 1) {
        s  += __shfl_xor_sync(0xffffffffu, s, o);
        s2 += __shfl_xor_sync(0xffffffffu, s2, o);
    }
    float m = s * (1.f / 256.f);
    float rstd = rsqrtf(s2 * (1.f / 256.f) - m * m + 1e-5f);
    int c = lane * 4;
    const float4* w4 = (const float4*)w;
    const float4* b4 = (const float4*)b;
    float4 wa = w4[lane], ba = b4[lane], wb = w4[lane + 32], bc = b4[lane + 32];
    uint2 oA, oB;
    oA.x = pack_bf16x2((v0.x - m) * rstd * wa.x + ba.x, (v0.y - m) * rstd * wa.y + ba.y);
    oA.y = pack_bf16x2((v0.z - m) * rstd * wa.z + ba.z, (v0.w - m) * rstd * wa.w + ba.w);
    oB.x = pack_bf16x2((v1.x - m) * rstd * wb.x + bc.x, (v1.y - m) * rstd * wb.y + bc.y);
    oB.y = pack_bf16x2((v1.z - m) * rstd * wb.z + bc.z, (v1.w - m) * rstd * wb.w + bc.w);
    *(uint2*)&g_xwin[(size_t)wt * CDIM + c] = oA;
    *(uint2*)&g_xwin[(size_t)wt * CDIM + c + 128] = oB;
}

// ---------------- plain LN2 (warp per token, token layout) --------------------
__global__ void __launch_bounds__(256) k_ln2(const float* __restrict__ w,
                                             const float* __restrict__ b) {
    int t0 = blockIdx.x * 8 + (threadIdx.x >> 5);
    int lane = threadIdx.x & 31;
    const float4* src = (const float4*)(g_x1 + (size_t)t0 * CDIM);
    float4 v0 = src[lane], v1 = src[lane + 32];
    float s = v0.x + v0.y + v0.z + v0.w + v1.x + v1.y + v1.z + v1.w;
    float s2 = v0.x*v0.x + v0.y*v0.y + v0.z*v0.z + v0.w*v0.w
             + v1.x*v1.x + v1.y*v1.y + v1.z*v1.z + v1.w*v1.w;
    #pragma unroll
    for (int o = 16; o > 0; o >>= 1) {
        s  += __shfl_xor_sync(0xffffffffu, s, o);
        s2 += __shfl_xor_sync(0xffffffffu, s2, o);
    }
    float m = s * (1.f / 256.f);
    float rstd = rsqrtf(s2 * (1.f / 256.f) - m * m + 1e-5f);
    int c = lane * 4;
    const float4* w4 = (const float4*)w;
    const float4* b4 = (const float4*)b;
    float4 wa = w4[lane], ba = b4[lane], wb = w4[lane + 32], bc = b4[lane + 32];
    uint2 oA, oB;
    oA.x = pack_bf16x2((v0.x - m) * rstd * wa.x + ba.x, (v0.y - m) * rstd * wa.y + ba.y);
    oA.y = pack_bf16x2((v0.z - m) * rstd * wa.z + ba.z, (v0.w - m) * rstd * wa.w + ba.w);
    oB.x = pack_bf16x2((v1.x - m) * rstd * wb.x + bc.x, (v1.y - m) * rstd * wb.y + bc.y);
    oB.y = pack_bf16x2((v1.z - m) * rstd * wb.z + bc.z, (v1.w - m) * rstd * wb.w + bc.w);
    *(uint2*)&g_xwin[(size_t)t0 * CDIM + c] = oA;
    *(uint2*)&g_xwin[(size_t)t0 * CDIM + c + 128] = oB;
}

// ============ bf16 mma GEMM ====================================================
// EPI: 0 = fp32 +bias; 1 = bf16 (+bias)*scale for col<256; 2 = bf16 gelu(+bias);
//      3 = fp32 +bias+res; 4 = fp32 x1[dst] = res[dst] + acc + bias (unshift gather)
#define STAGE_B 8192

__device__ __forceinline__ void load_stage_bf(uint32_t sb, int s,
                                              const __nv_bfloat16* __restrict__ Ab,
                                              const __nv_bfloat16* __restrict__ Bb,
                                              int K, int kc, int tid) {
    const __nv_bfloat16* Ag = Ab + kc * 32;
    const __nv_bfloat16* Bg = Bb + kc * 32;
    uint32_t abase = sb + s * STAGE_B;
    uint32_t bbase = sb + 3 * STAGE_B + s * STAGE_B;
    #pragma unroll
    for (int i = 0; i < 2; i++) {
        int idx = tid + (i << 8);
        int row = idx >> 2, ch = idx & 3;
        int sw = ch ^ ((row >> 1) & 3);
        CP_ASYNC16(abase + row * 64 + sw * 16, Ag + (size_t)row * K + ch * 8);
        CP_ASYNC16(bbase + row * 64 + sw * 16, Bg + (size_t)row * K + ch * 8);
    }
    CP_COMMIT();
}

template <int EPI>
__global__ void __launch_bounds__(256) k_gemm_bf16(
    const __nv_bfloat16* __restrict__ A, const __nv_bfloat16* __restrict__ Bt,
    const float* __restrict__ bias, void* __restrict__ Cout,
    int K, int Ntot, float scale, const float* __restrict__ res)
{
    __shared__ __align__(16) char smem[6 * STAGE_B];
    uint32_t sb = smem_u32(smem);

    int tid = threadIdx.x, lane = tid & 31, wid = tid >> 5;
    int wm = wid >> 2, wn = wid & 3;
    int bm = blockIdx.y << 7, bn = blockIdx.x << 7;
    const __nv_bfloat16* Ab = A + (size_t)bm * K;
    const __nv_bfloat16* Bb = Bt + (size_t)bn * K;
    int nKC = K >> 5;

    int rA = (lane & 7) + ((lane >> 3) & 1) * 8;
    int cA = lane >> 4;
    int selA = (rA >> 1) & 3;
    uint32_t aRowOff = (uint32_t)(wm * 64 + rA) * 64;
    uint32_t aChunkOff[2] = { (uint32_t)((0 + cA) ^ selA) * 16,
                              (uint32_t)((2 + cA) ^ selA) * 16 };
    int rB = lane & 7, cB = lane >> 3;
    int selB = (rB >> 1) & 3;
    uint32_t bOff = (uint32_t)(wn * 32 + rB) * 64 + (uint32_t)(cB ^ selB) * 16;

    float acc[4][4][4];
    #pragma unroll
    for (int mt = 0; mt < 4; mt++)
        #pragma unroll
        for (int nt = 0; nt < 4; nt++)
            #pragma unroll
            for (int q = 0; q < 4; q++) acc[mt][nt][q] = 0.f;

    load_stage_bf(sb, 0, Ab, Bb, K, 0, tid);
    if (nKC > 1) load_stage_bf(sb, 1, Ab, Bb, K, 1, tid);
    else CP_COMMIT();

    for (int kc = 0; kc < nKC; kc++) {
        if (kc + 2 < nKC) { load_stage_bf(sb, (kc + 2) % 3, Ab, Bb, K, kc + 2, tid); CP_WAIT_2(); }
        else if (kc + 1 < nKC) { CP_WAIT_1(); }
        else { CP_WAIT_0(); }
        __syncthreads();

        uint32_t asp = sb + (kc % 3) * STAGE_B;
        uint32_t bsp = sb + 3 * STAGE_B + (kc % 3) * STAGE_B;

        uint32_t bfr[4][4];
        #pragma unroll
        for (int nt = 0; nt < 4; nt++)
            LDMATRIX_X4(bfr[nt][0], bfr[nt][1], bfr[nt][2], bfr[nt][3],
                        bsp + bOff + nt * 512);
        #pragma unroll
        for (int kk = 0; kk < 2; kk++) {
            #pragma unroll
            for (int mt = 0; mt < 4; mt++) {
                uint32_t a0, a1, a2, a3;
                LDMATRIX_X4(a0, a1, a2, a3, asp + aRowOff + mt * 1024 + aChunkOff[kk]);
                #pragma unroll
                for (int nt = 0; nt < 4; nt++)
                    MMA_BF16(acc[mt][nt], a0, a1, a2, a3,
                             bfr[nt][kk * 2], bfr[nt][kk * 2 + 1]);
            }
        }
        __syncthreads();
    }

    int g = lane >> 2, t = lane & 3;
    #pragma unroll
    for (int mt = 0; mt < 4; mt++) {
        int r0 = bm + wm * 64 + mt * 16 + g;
        int r1 = r0 + 8;
        size_t d0, d1;
        if (EPI == 4) {
            d0 = (size_t)wt2dst(r0) * 256;
            d1 = (size_t)wt2dst(r1) * 256;
        } else {
            d0 = (size_t)r0 * Ntot;
            d1 = (size_t)r1 * Ntot;
        }
        #pragma unroll
        for (int nt = 0; nt < 4; nt++) {
            int c0 = bn + wn * 32 + nt * 8 + t * 2;
            float2 b2 = *(const float2*)&bias[c0];
            float v00 = acc[mt][nt][0] + b2.x;
            float v01 = acc[mt][nt][1] + b2.y;
            float v10 = acc[mt][nt][2] + b2.x;
            float v11 = acc[mt][nt][3] + b2.y;
            if (EPI == 1) {
                if (c0 < 256) { v00 *= scale; v01 *= scale; v10 *= scale; v11 *= scale; }
            }
            if (EPI == 2) {
                v00 = 0.5f * v00 * (1.f + erff(v00 * 0.70710678118654752f));
                v01 = 0.5f * v01 * (1.f + erff(v01 * 0.70710678118654752f));
                v10 = 0.5f * v10 * (1.f + erff(v10 * 0.70710678118654752f));
                v11 = 0.5f * v11 * (1.f + erff(v11 * 0.70710678118654752f));
            }
            if (EPI == 3 || EPI == 4) {
                float2 ra = *(const float2*)&res[d0 + c0];
                float2 rb = *(const float2*)&res[d1 + c0];
                v00 += ra.x; v01 += ra.y; v10 += rb.x; v11 += rb.y;
            }
            if (EPI == 0 || EPI == 3 || EPI == 4) {
                float* C = (float*)Cout;
                float2 oa; oa.x = v00; oa.y = v01;
                float2 ob; ob.x = v10; ob.y = v11;
                *(float2*)&C[d0 + c0] = oa;
                *(float2*)&C[d1 + c0] = ob;
            } else {
                __nv_bfloat16* C = (__nv_bfloat16*)Cout;
                *(uint32_t*)&C[d0 + c0] = pack_bf16x2(v00, v01);
                *(uint32_t*)&C[d1 + c0] = pack_bf16x2(v10, v11);
            }
        }
    }
}

// ================= mma-based windowed attention ================================
#define ATT_SMEM (3 * 32768 + 1800 * 4)

__global__ void __launch_bounds__(512) k_attn2(const float* __restrict__ rpb) {
    extern __shared__ __align__(16) char sm[];
    uint32_t sb = smem_u32(sm);
    float* srpb = (float*)(sm + 98304);

    int wglob = blockIdx.x;
    int win = wglob & 255;
    int wh = win >> 4, ww = win & 15;
    int wt0 = wglob << 6;
    int tid = threadIdx.x;

    for (int iv = tid; iv < 6144; iv += 512) {
        int mat = iv >> 11;
        int rem = iv & 2047;
        int row = rem >> 5, ch = rem & 31;
        uint4 v = *(const uint4*)&g_qkv[(size_t)(wt0 + row) * 768 + mat * 256 + ch * 8];
        *(uint4*)(sm + mat * 32768 + row * 512 + ((ch ^ (row & 7)) << 4)) = v;
    }
    for (int iv = tid; iv < 1800; iv += 512) srpb[iv] = rpb[iv];
    __syncthreads();

    int lane = tid & 31, wid = tid >> 5;
    int h = wid >> 1, mh = wid & 1;
    int m0 = mh * 32;
    int g = lane >> 2, t = lane & 3;
    uint32_t sQ = sb, sK = sb + 32768, sV = sb + 65536;

    float S[2][8][4];
    #pragma unroll
    for (int mt = 0; mt < 2; mt++)
        #pragma unroll
        for (int nt = 0; nt < 8; nt++)
            #pragma unroll
            for (int q = 0; q < 4; q++) S[mt][nt][q] = 0.f;

    #pragma unroll
    for (int s = 0; s < 2; s++) {
        uint32_t a[2][4];
        #pragma unroll
        for (int mt = 0; mt < 2; mt++) {
            int row = m0 + mt * 16 + (lane & 15);
            int ch = h * 4 + s * 2 + (lane >> 4);
            LDMATRIX_X4(a[mt][0], a[mt][1], a[mt][2], a[mt][3],
                        sQ + row * 512 + (((ch) ^ (row & 7)) << 4));
        }
        uint32_t bb[8][2];
        #pragma unroll
        for (int p = 0; p < 4; p++) {
            int row = p * 16 + (lane & 7) + ((lane >> 4) & 1) * 8;
            int ch = h * 4 + s * 2 + ((lane >> 3) & 1);
            LDMATRIX_X4(bb[2 * p][0], bb[2 * p][1], bb[2 * p + 1][0], bb[2 * p + 1][1],
                        sK + row * 512 + ((ch ^ (row & 7)) << 4));
        }
        #pragma unroll
        for (int mt = 0; mt < 2; mt++)
            #pragma unroll
            for (int nt = 0; nt < 8; nt++)
                MMA_BF16(S[mt][nt], a[mt][0], a[mt][1], a[mt][2], a[mt][3],
                         bb[nt][0], bb[nt][1]);
    }

    int mwh = (wh == 15), mww = (ww == 15);
    int jc0 = t * 2, jc1 = t * 2 + 1;
    int cregj0 = mww ? (jc0 < 4 ? 1 : 2) : 0;
    int cregj1 = mww ? (jc1 < 4 ? 1 : 2) : 0;

    uint32_t pa[2][4][4];
    #pragma unroll
    for (int mt = 0; mt < 2; mt++) {
        int r0 = m0 + mt * 16 + g;
        int r1 = r0 + 8;
        int ir0 = r0 >> 3, jr0 = r0 & 7;
        int ir1 = r1 >> 3;
        int rregi0 = mwh ? (ir0 < 4 ? 1 : 2) : 0;
        int rregi1 = mwh ? (ir1 < 4 ? 1 : 2) : 0;
        int rregj = mww ? (jr0 < 4 ? 1 : 2) : 0;
        int reg0 = rregi0 * 3 + rregj;
        int reg1 = rregi1 * 3 + rregj;
        float mx0 = -1e30f, mx1 = -1e30f;
        #pragma unroll
        for (int nt = 0; nt < 8; nt++) {
            int cregi = mwh ? (nt < 4 ? 1 : 2) : 0;
            int base0 = (ir0 - nt + 7) * 15 + jr0 + 7;
            int base1 = (ir1 - nt + 7) * 15 + jr0 + 7;
            float b00 = srpb[(base0 - jc0) * 8 + h];
            float b01 = srpb[(base0 - jc1) * 8 + h];
            float b10 = srpb[(base1 - jc0) * 8 + h];
            float b11 = srpb[(base1 - jc1) * 8 + h];
            int c0r = cregi * 3 + cregj0, c1r = cregi * 3 + cregj1;
            S[mt][nt][0] += b00 + ((c0r != reg0) ? -100.f : 0.f);
            S[mt][nt][1] += b01 + ((c1r != reg0) ? -100.f : 0.f);
            S[mt][nt][2] += b10 + ((c0r != reg1) ? -100.f : 0.f);
            S[mt][nt][3] += b11 + ((c1r != reg1) ? -100.f : 0.f);
            mx0 = fmaxf(mx0, fmaxf(S[mt][nt][0], S[mt][nt][1]));
            mx1 = fmaxf(mx1, fmaxf(S[mt][nt][2], S[mt][nt][3]));
        }
        mx0 = fmaxf(mx0, __shfl_xor_sync(0xffffffffu, mx0, 1));
        mx0 = fmaxf(mx0, __shfl_xor_sync(0xffffffffu, mx0, 2));
        mx1 = fmaxf(mx1, __shfl_xor_sync(0xffffffffu, mx1, 1));
        mx1 = fmaxf(mx1, __shfl_xor_sync(0xffffffffu, mx1, 2));
        float sum0 = 0.f, sum1 = 0.f;
        #pragma unroll
        for (int nt = 0; nt < 8; nt++) {
            S[mt][nt][0] = expf(S[mt][nt][0] - mx0);
            S[mt][nt][1] = expf(S[mt][nt][1] - mx0);
            S[mt][nt][2] = expf(S[mt][nt][2] - mx1);
            S[mt][nt][3] = expf(S[mt][nt][3] - mx1);
            sum0 += S[mt][nt][0] + S[mt][nt][1];
            sum1 += S[mt][nt][2] + S[mt][nt][3];
        }
        sum0 += __shfl_xor_sync(0xffffffffu, sum0, 1);
        sum0 += __shfl_xor_sync(0xffffffffu, sum0, 2);
        sum1 += __shfl_xor_sync(0xffffffffu, sum1, 1);
        sum1 += __shfl_xor_sync(0xffffffffu, sum1, 2);
        float inv0 = 1.f / sum0, inv1 = 1.f / sum1;
        #pragma unroll
        for (int s = 0; s < 4; s++) {
            pa[mt][s][0] = pack_bf16x2(S[mt][2*s][0] * inv0, S[mt][2*s][1] * inv0);
            pa[mt][s][1] = pack_bf16x2(S[mt][2*s][2] * inv1, S[mt][2*s][3] * inv1);
            pa[mt][s][2] = pack_bf16x2(S[mt][2*s+1][0] * inv0, S[mt][2*s+1][1] * inv0);
            pa[mt][s][3] = pack_bf16x2(S[mt][2*s+1][2] * inv1, S[mt][2*s+1][3] * inv1);
        }
    }

    float O[2][4][4];
    #pragma unroll
    for (int mt = 0; mt < 2; mt++)
        #pragma unroll
        for (int dt = 0; dt < 4; dt++)
            #pragma unroll
            for (int q = 0; q < 4; q++) O[mt][dt][q] = 0.f;

    #pragma unroll
    for (int s = 0; s < 4; s++) {
        uint32_t pb[4][2];
        #pragma unroll
        for (int half = 0; half < 2; half++) {
            int row = s * 16 + (lane & 7) + ((lane >> 3) & 1) * 8;
            int ch = h * 4 + half * 2 + (lane >> 4);
            LDMATRIX_X4_T(pb[half*2][0], pb[half*2][1], pb[half*2+1][0], pb[half*2+1][1],
                          sV + row * 512 + ((ch ^ (row & 7)) << 4));
        }
        #pragma unroll
        for (int mt = 0; mt < 2; mt++)
            #pragma unroll
            for (int dt = 0; dt < 4; dt++)
                MMA_BF16(O[mt][dt], pa[mt][s][0], pa[mt][s][1], pa[mt][s][2], pa[mt][s][3],
                         pb[dt][0], pb[dt][1]);
    }

    #pragma unroll
    for (int mt = 0; mt < 2; mt++) {
        int r0 = wt0 + m0 + mt * 16 + g;
        #pragma unroll
        for (int dt = 0; dt < 4; dt++) {
            int col = h * 32 + dt * 8 + t * 2;
            *(uint32_t*)&g_o[(size_t)r0 * 256 + col]       = pack_bf16x2(O[mt][dt][0], O[mt][dt][1]);
            *(uint32_t*)&g_o[(size_t)(r0 + 8) * 256 + col] = pack_bf16x2(O[mt][dt][2], O[mt][dt][3]);
        }
    }
}

// ---------------- depthwise 3x3 conv + bias + GELU (column rotation) ----------
__device__ __forceinline__ float4 ldh4(const __nv_bfloat16* base, int yy, int xx, int c0) {
    if ((unsigned)yy > 127u || (unsigned)xx > 127u) return make_float4(0.f, 0.f, 0.f, 0.f);
    uint2 hv = *(const uint2*)&base[((size_t)(yy * WDIM + xx)) * HIDDIM + c0];
    return make_float4(bflo(hv.x), bfhi(hv.x), bflo(hv.y), bfhi(hv.y));
}

__global__ void __launch_bounds__(256) k_dwconv(const float* __restrict__ w9,
                                                const float* __restrict__ bconv) {
    __shared__ float wsm[HIDDIM * 9];
    int tid = threadIdx.x;
    for (int e = tid; e < HIDDIM * 9; e += 256) wsm[e] = w9[e];
    __syncthreads();

    int c0 = tid * 4;
    float wr[4][9];
    #pragma unroll
    for (int q = 0; q < 4; q++)
        #pragma unroll
        for (int k = 0; k < 9; k++) wr[q][k] = wsm[(c0 + q) * 9 + k];
    float4 bia = *(const float4*)&bconv[c0];

    int p0 = blockIdx.x * 16;
    int bb = p0 >> 14;
    int y  = (p0 >> 7) & 127;
    int x0 = p0 & 127;
    const __nv_bfloat16* base = g_h + (size_t)bb * LTOK * HIDDIM;
    __nv_bfloat16* outb = g_h2 + (size_t)bb * LTOK * HIDDIM;

    float4 L[3], Cc[3], R[3];
    #pragma unroll
    for (int dy = 0; dy < 3; dy++) {
        L[dy]  = ldh4(base, y + dy - 1, x0 - 1, c0);
        Cc[dy] = ldh4(base, y + dy - 1, x0, c0);
    }

    for (int px = 0; px < 16; px++) {
        int xx = x0 + px;
        #pragma unroll
        for (int dy = 0; dy < 3; dy++) R[dy] = ldh4(base, y + dy - 1, xx + 1, c0);
        float a0 = bia.x, a1 = bia.y, a2 = bia.z, a3 = bia.w;
        #pragma unroll
        for (int dy = 0; dy < 3; dy++) {
            a0 = fmaf(L[dy].x,  wr[0][dy*3+0], a0);
            a0 = fmaf(Cc[dy].x, wr[0][dy*3+1], a0);
            a0 = fmaf(R[dy].x,  wr[0][dy*3+2], a0);
            a1 = fmaf(L[dy].y,  wr[1][dy*3+0], a1);
            a1 = fmaf(Cc[dy].y, wr[1][dy*3+1], a1);
            a1 = fmaf(R[dy].y,  wr[1][dy*3+2], a1);
            a2 = fmaf(L[dy].z,  wr[2][dy*3+0], a2);
            a2 = fmaf(Cc[dy].z, wr[2][dy*3+1], a2);
            a2 = fmaf(R[dy].z,  wr[2][dy*3+2], a2);
            a3 = fmaf(L[dy].w,  wr[3][dy*3+0], a3);
            a3 = fmaf(Cc[dy].w, wr[3][dy*3+1], a3);
            a3 = fmaf(R[dy].w,  wr[3][dy*3+2], a3);
        }
        a0 = 0.5f * a0 * (1.f + erff(a0 * 0.70710678118654752f));
        a1 = 0.5f * a1 * (1.f + erff(a1 * 0.70710678118654752f));
        a2 = 0.5f * a2 * (1.f + erff(a2 * 0.70710678118654752f));
        a3 = 0.5f * a3 * (1.f + erff(a3 * 0.70710678118654752f));
        uint2 ov;
        ov.x = pack_bf16x2(a0, a1);
        ov.y = pack_bf16x2(a2, a3);
        *(uint2*)&outb[((size_t)(y * WDIM + xx)) * HIDDIM + c0] = ov;
        #pragma unroll
        for (int dy = 0; dy < 3; dy++) { L[dy] = Cc[dy]; Cc[dy] = R[dy]; }
    }
}

// ---------------- launch -------------------------------------------------------
extern "C" void kernel_launch(void* const* d_in, const int* in_sizes, int n_in,
                              void* d_out, int out_size) {
    const float* x       = (const float*)d_in[0];
    const float* norm1_w = (const float*)d_in[3];
    const float* norm1_b = (const float*)d_in[4];
    const float* wq      = (const float*)d_in[5];
    const float* bq      = (const float*)d_in[6];
    const float* wkv     = (const float*)d_in[7];
    const float* bkv     = (const float*)d_in[8];
    const float* rpb     = (const float*)d_in[9];
    const float* proj_w  = (const float*)d_in[10];
    const float* proj_b  = (const float*)d_in[11];
    const float* norm2_w = (const float*)d_in[12];
    const float* norm2_b = (const float*)d_in[13];
    const float* lin1_w  = (const float*)d_in[14];
    const float* lin1_b  = (const float*)d_in[15];
    const float* dw_w    = (const float*)d_in[16];
    const float* dw_b    = (const float*)d_in[17];
    const float* lin2_w  = (const float*)d_in[18];
    const float* lin2_b  = (const float*)d_in[19];
    float* out = (float*)d_out;

    __nv_bfloat16 *p_xwin, *p_qkv, *p_o, *p_h, *p_h2, *p_wqkv, *p_wproj, *p_wl1, *p_wl2;
    float *p_x1, *p_bqkv;
    cudaGetSymbolAddress((void**)&p_xwin,  g_xwin);
    cudaGetSymbolAddress((void**)&p_qkv,   g_qkv);
    cudaGetSymbolAddress((void**)&p_o,     g_o);
    cudaGetSymbolAddress((void**)&p_x1,    g_x1);
    cudaGetSymbolAddress((void**)&p_h,     g_h);
    cudaGetSymbolAddress((void**)&p_h2,    g_h2);
    cudaGetSymbolAddress((void**)&p_wqkv,  g_wqkv_t);
    cudaGetSymbolAddress((void**)&p_wproj, g_wproj_t);
    cudaGetSymbolAddress((void**)&p_wl1,   g_wlin1_t);
    cudaGetSymbolAddress((void**)&p_wl2,   g_wlin2_t);
    cudaGetSymbolAddress((void**)&p_bqkv,  g_bqkv);

    cudaFuncSetAttribute(k_attn2, cudaFuncAttributeMaxDynamicSharedMemorySize, ATT_SMEM);

    const float scale = 0.17677669529663687f;

    // merged weight prep
    k_prep_all<<<2304, 256>>>(wq, wkv, bq, bkv, proj_w, lin1_w, lin2_w);
    // LN1 + gather
    k_ln1_gather<<<NTOK / 8, 256>>>(x, norm1_w, norm1_b);
    // qkv
    k_gemm_bf16<1><<<dim3(6, NTOK / 128), 256>>>(
        p_xwin, p_wqkv, p_bqkv, p_qkv, 256, 768, scale, nullptr);
    // attention
    k_attn2<<<NTOK / 64, 512, ATT_SMEM>>>(rpb);
    // proj + unshift-gather + residual -> x1 (fp32, token layout)
    k_gemm_bf16<4><<<dim3(2, NTOK / 128), 256>>>(
        p_o, p_wproj, proj_b, p_x1, 256, 256, 1.f, x);
    // LN2
    k_ln2<<<NTOK / 8, 256>>>(norm2_w, norm2_b);
    // lin1 + gelu
    k_gemm_bf16<2><<<dim3(8, NTOK / 128), 256>>>(
        p_xwin, p_wl1, lin1_b, p_h, 256, 1024, 1.f, nullptr);
    // depthwise conv + gelu
    k_dwconv<<<NTOK / 16, 256>>>(dw_w, dw_b);
    // lin2 + residual -> out
    k_gemm_bf16<3><<<dim3(2, NTOK / 128), 256>>>(
        p_h2, p_wl2, lin2_b, out, 1024, 256, 1.f, p_x1);
}